// round 14
// baseline (speedup 1.0000x reference)
#include <cuda_runtime.h>
#include <math.h>
#include <float.h>

typedef unsigned int u32;

static constexpr int NB = 8, N1 = 4096, N2 = 2048, N3 = 512, KNN = 32;

// ---------------- scratch ----------------
__device__ int   g_idx1[NB * N1 * KNN];
__device__ int   g_cnt1[NB * N1];
__device__ float g_a1  [NB * N1 * 64];
__device__ float g_x1  [NB * N1 * 64];
__device__ int   g_fi1 [NB * N2];
__device__ float g_pos2[NB * N2 * 3];
__device__ float g_x2g [NB * N2 * 64];
__device__ float g_a2  [NB * N2 * 128];
__device__ int   g_idx2[NB * N2 * KNN];
__device__ int   g_cnt2[NB * N2];
__device__ float g_x2  [NB * N2 * 128];
__device__ int   g_fi2 [NB * N3];
__device__ float g_pos3[NB * N3 * 3];
__device__ float g_x3g [NB * N3 * 128];
__device__ float g_a3  [NB * N3 * 256];
__device__ int   g_idx3[NB * N3 * KNN];
__device__ int   g_cnt3[NB * N3];
__device__ float g_x3  [NB * N3 * 256];
__device__ int   g_perm1[NB * N1];
__device__ int   g_perm2[NB * N2];
__device__ int   g_perm3[NB * N3];
__device__ u32   g_w2t1[4096];
__device__ u32   g_w2t2[16384];
__device__ u32   g_w2t3[65536];

// ---------------- tf32 helpers ----------------
__device__ __forceinline__ u32 f2tf32(float f) {
    u32 r; asm("cvt.rna.tf32.f32 %0,%1;" : "=r"(r) : "f"(f)); return r;
}
__device__ __forceinline__ void mma_tf32(float* d, const u32* A, u32 b0, u32 b1) {
    asm("mma.sync.aligned.m16n8k8.row.col.f32.tf32.tf32.f32 "
        "{%0,%1,%2,%3},{%4,%5,%6,%7},{%8,%9},{%0,%1,%2,%3};"
        : "+f"(d[0]), "+f"(d[1]), "+f"(d[2]), "+f"(d[3])
        : "r"(A[0]), "r"(A[1]), "r"(A[2]), "r"(A[3]), "r"(b0), "r"(b1));
}

// ---------------- W2 -> tf32 fragment-major precompute ----------------
template <int CHID, int COUT>
__global__ void __launch_bounds__(256)
w2t_pre_kernel(const float* __restrict__ W2, u32* __restrict__ W2T)
{
    constexpr int NW = COUT / 32;
    int tid = blockIdx.x * 256 + threadIdx.x;
    int lane8 = tid & 255;
    int lane = lane8 >> 3, n = (lane8 & 7) >> 1, r = lane8 & 1;
    int rest = tid >> 8;
    int w = rest % NW, kt = rest / NW;
    int k = kt * 8 + (lane & 3) + r * 4;
    int c = w * 32 + n * 8 + (lane >> 2);
    W2T[tid] = f2tf32(W2[k * COUT + c]);
}

// ---------------- spatial counting sort ----------------
template <int NBIN>
__global__ void __launch_bounds__(256)
binsort_kernel(const float* __restrict__ pos, int N, int* __restrict__ perm)
{
    constexpr int B3 = NBIN * NBIN * NBIN;
    __shared__ int hist[B3];
    __shared__ int offs[B3];
    const int b = blockIdx.x, t = threadIdx.x;
    const float* pb = pos + (size_t)b * N * 3;

    for (int e = t; e < B3; e += 256) hist[e] = 0;
    __syncthreads();
    for (int i = t; i < N; i += 256) {
        int ix = min(NBIN - 1, max(0, (int)(pb[i * 3 + 0] * NBIN)));
        int iy = min(NBIN - 1, max(0, (int)(pb[i * 3 + 1] * NBIN)));
        int iz = min(NBIN - 1, max(0, (int)(pb[i * 3 + 2] * NBIN)));
        atomicAdd(&hist[(ix * NBIN + iy) * NBIN + iz], 1);
    }
    __syncthreads();
    if (t == 0) {
        int acc = 0;
        for (int k = 0; k < B3; ++k) { offs[k] = acc; acc += hist[k]; }
    }
    __syncthreads();
    for (int e = t; e < B3; e += 256) hist[e] = 0;
    __syncthreads();
    for (int i = t; i < N; i += 256) {
        int ix = min(NBIN - 1, max(0, (int)(pb[i * 3 + 0] * NBIN)));
        int iy = min(NBIN - 1, max(0, (int)(pb[i * 3 + 1] * NBIN)));
        int iz = min(NBIN - 1, max(0, (int)(pb[i * 3 + 2] * NBIN)));
        int key = (ix * NBIN + iy) * NBIN + iz;
        int r = offs[key] + atomicAdd(&hist[key], 1);
        perm[b * N + r] = i;
    }
}

// ---------------- node_pre as tiled GEMM: a = [x,pos] @ W1 + b1 ----------
// Block: MT nodes x CHID cols. Thread: NPG nodes x 4 cols in registers.
// Accumulation order (b1, then f ascending) matches the scalar version
// exactly -> bit-identical output.
template <int CINX, int CHID, int MT>
__global__ void __launch_bounds__(256)
node_gemm_kernel(const float* __restrict__ x, const float* __restrict__ pos,
                 const float* __restrict__ W1, const float* __restrict__ b1,
                 float* __restrict__ a)
{
    constexpr int CINF = CINX + 3;
    constexpr int FP = CINF + 1;
    constexpr int CG = CHID / 4;
    constexpr int NG = 256 / CG;
    constexpr int NPG = MT / NG;
    __shared__ float xs[MT][FP];
    const int t = threadIdx.x;
    const int nodeBase = blockIdx.x * MT;

    for (int e = t; e < MT * CINF; e += 256) {
        int n = e / CINF, f = e - n * CINF;
        int node = nodeBase + n;
        float v = (f < CINX) ? x[(size_t)node * CINX + f]
                             : pos[(size_t)node * 3 + (f - CINX)];
        xs[n][f] = v;
    }
    __syncthreads();

    const int c0 = (t % CG) * 4;
    const int n0 = (t / CG) * NPG;
    float4 acc[NPG];
    const float4 bb = *(const float4*)&b1[c0];
#pragma unroll
    for (int n = 0; n < NPG; ++n) acc[n] = bb;

#pragma unroll 2
    for (int f = 0; f < CINF; ++f) {
        float4 w = *(const float4*)&W1[f * CHID + c0];
#pragma unroll
        for (int n = 0; n < NPG; ++n) {
            float s = xs[n0 + n][f];
            acc[n].x = fmaf(s, w.x, acc[n].x);
            acc[n].y = fmaf(s, w.y, acc[n].y);
            acc[n].z = fmaf(s, w.z, acc[n].z);
            acc[n].w = fmaf(s, w.w, acc[n].w);
        }
    }
#pragma unroll
    for (int n = 0; n < NPG; ++n)
        *(float4*)&a[(size_t)(nodeBase + n0 + n) * CHID + c0] = acc[n];
}

// ---------------- KNN (512 thr), register top-32, bin-coherent queries ----
__device__ void knn_dev(const float* __restrict__ pb, int N, float r2v,
                        int* __restrict__ oidx, int* __restrict__ ocnt,
                        int qb, const int* __restrict__ perm, float4* sj)
{
    const int t = threadIdx.x;
    const int i = perm[qb * 512 + t];
    const float xi = pb[i * 3 + 0], yi = pb[i * 3 + 1], zi = pb[i * 3 + 2];
    const float sqi = __fadd_rn(__fadd_rn(__fmul_rn(xi, xi), __fmul_rn(yi, yi)),
                                __fmul_rn(zi, zi));
    const float m2x = -2.f * xi, m2y = -2.f * yi, m2z = -2.f * zi;

    float bd[KNN];
    int   bi_[KNN];
#pragma unroll
    for (int k = 0; k < KNN; ++k) { bd[k] = FLT_MAX; bi_[k] = 0; }
    float worst = FLT_MAX;

    for (int t0 = 0; t0 < N; t0 += 512) {
        __syncthreads();
        {
            int j = t0 + t;
            float x = pb[j * 3 + 0], y = pb[j * 3 + 1], z = pb[j * 3 + 2];
            float sq = __fadd_rn(__fadd_rn(__fmul_rn(x, x), __fmul_rn(y, y)),
                                 __fmul_rn(z, z));
            sj[t] = make_float4(x, y, z, sq);
        }
        __syncthreads();
#pragma unroll 2
        for (int jj = 0; jj < 512; ++jj) {
            float4 q = sj[jj];
            float d2 = sqi + fmaf(m2x, q.x, fmaf(m2y, q.y, fmaf(m2z, q.z, q.w)));
            int j = t0 + jj;
            if (d2 <= r2v && d2 < worst && j != i) {
#pragma unroll
                for (int k = KNN - 1; k > 0; --k) {
                    if (bd[k - 1] > d2)  { bd[k] = bd[k - 1]; bi_[k] = bi_[k - 1]; }
                    else if (bd[k] > d2) { bd[k] = d2;        bi_[k] = j; }
                }
                if (bd[0] > d2)          { bd[0] = d2;        bi_[0] = j; }
                worst = bd[KNN - 1];
            }
        }
    }
    int cnt = 0;
#pragma unroll
    for (int k = 0; k < KNN; ++k) cnt += (bd[k] <= r2v) ? 1 : 0;
    ocnt[i] = cnt;
    const int base = i * KNN;
#pragma unroll
    for (int k = 0; k < KNN; ++k) oidx[base + k] = bi_[k];
}

__global__ void __launch_bounds__(512, 1)
knn_kernel(const float* __restrict__ pos, int N, float r2v,
           int* __restrict__ oidx, int* __restrict__ ocnt,
           const int* __restrict__ perm)
{
    extern __shared__ char sm[];
    int b = blockIdx.x % NB, qb = blockIdx.x / NB;
    knn_dev(pos + (size_t)b * N * 3, N, r2v,
            oidx + (size_t)b * N * KNN, ocnt + b * N, qb,
            perm + b * N, (float4*)sm);
}

// ---------------- FPS (512 threads), standalone kernel -------------------
template <int P>
__global__ void __launch_bounds__(512, 1)
fps_kernel(const float* __restrict__ pos, int nS, int* __restrict__ fi)
{
    extern __shared__ char sm[];
    float* smf = (float*)sm;
    const int N = P * 512;
    const float* pb = pos + (size_t)blockIdx.x * N * 3;
    int* out = fi + blockIdx.x * nS;
    float* spos = smf;
    u32*  svb = (u32*)(smf + N * 3);
    int*  si  = (int*)(svb + 32);
    const int t = threadIdx.x, w = t >> 5, l = t & 31;

    for (int e = t; e < N * 3; e += 512) spos[e] = pb[e];
    __syncthreads();

    float px[P], py[P], pz[P], mind[P];
    const float x0 = spos[0], y0 = spos[1], z0 = spos[2];
    float bv = -1.f; int bidx = 0x7fffffff;
#pragma unroll
    for (int p = 0; p < P; ++p) {
        int i = t + p * 512;
        px[p] = spos[i * 3 + 0]; py[p] = spos[i * 3 + 1]; pz[p] = spos[i * 3 + 2];
        float dx = px[p] - x0, dy = py[p] - y0, dz = pz[p] - z0;
        mind[p] = __fadd_rn(__fadd_rn(__fmul_rn(dx, dx), __fmul_rn(dy, dy)),
                            __fmul_rn(dz, dz));
        if (mind[p] > bv) { bv = mind[p]; bidx = i; }
    }
    if (t == 0) out[0] = 0;

    int par = 0;
    for (int s = 1; s < nS; ++s) {
        u32 vb = __float_as_uint(bv);
        u32 m  = __reduce_max_sync(0xffffffffu, vb);
        u32 cand = (vb == m) ? (u32)bidx : 0xffffffffu;
        u32 wi = __reduce_min_sync(0xffffffffu, cand);
        if (l == 0) { svb[par * 16 + w] = m; si[par * 16 + w] = (int)wi; }
        __syncthreads();
        u32 v2 = (l < 16) ? svb[par * 16 + l] : 0u;
        u32 i2 = (l < 16) ? (u32)si[par * 16 + l] : 0xffffffffu;
        u32 m2 = __reduce_max_sync(0xffffffffu, v2);
        u32 c2 = (v2 == m2 && l < 16) ? i2 : 0xffffffffu;
        u32 gi = __reduce_min_sync(0xffffffffu, c2);
        if (t == 0) out[s] = (int)gi;
        const float cx = spos[gi * 3 + 0];
        const float cy = spos[gi * 3 + 1];
        const float cz = spos[gi * 3 + 2];
        par ^= 1;
        bv = -1.f; bidx = 0x7fffffff;
#pragma unroll
        for (int p = 0; p < P; ++p) {
            float dx = px[p] - cx, dy = py[p] - cy, dz = pz[p] - cz;
            float d = __fadd_rn(__fadd_rn(__fmul_rn(dx, dx), __fmul_rn(dy, dy)),
                                __fmul_rn(dz, dz));
            mind[p] = fminf(mind[p], d);
            if (mind[p] > bv) { bv = mind[p]; bidx = t + p * 512; }
        }
    }
}

// ---------------- pos-only gather (FPS stream) ----------------
__global__ void posgather_kernel(const float* __restrict__ posin,
                                 const int* __restrict__ fi,
                                 float* __restrict__ poso, int Nin, int Nout)
{
    const int tid = blockIdx.x * blockDim.x + threadIdx.x;
    const int tot = NB * Nout * 3;
    if (tid >= tot) return;
    int d = tid % 3, m = (tid / 3) % Nout, b = tid / (3 * Nout);
    int j = fi[b * Nout + m];
    poso[tid] = posin[((size_t)b * Nin + j) * 3 + d];
}

// ---------------- feature gather (main stream) ----------------
__global__ void xgather_kernel(const float* __restrict__ xin,
                               const int* __restrict__ fi,
                               float* __restrict__ xo, int Nin, int Nout, int C)
{
    const int tid = blockIdx.x * blockDim.x + threadIdx.x;
    const int stride = gridDim.x * blockDim.x;
    const int tot = NB * Nout * C;
    for (int e = tid; e < tot; e += stride) {
        int c = e % C, m = (e / C) % Nout, b = e / (C * Nout);
        int j = fi[b * Nout + m];
        xo[e] = xin[((size_t)b * Nin + j) * C + c];
    }
}

// ---------------- PointNetConv on tensor cores (tf32, preconverted W) ----
template <int CHID, int COUT>
__global__ void __launch_bounds__(256)
conv_mma_kernel(const float* __restrict__ a, const float* __restrict__ pos,
                const int* __restrict__ kidx, const int* __restrict__ kcnt,
                const float* __restrict__ W1p, const u32* __restrict__ W2T,
                const float* __restrict__ b2, float* __restrict__ xout, int N)
{
    constexpr int NW  = COUT / 32;
    constexpr int TPG = COUT;
    constexpr int PPB = 256 / TPG;
    constexpr int KT  = CHID / 8;
    constexpr int HS  = 40;
    constexpr int GSZ = CHID * HS + CHID;
    extern __shared__ char sm[];
    float* smem = (float*)sm;
    const int tg = threadIdx.x / TPG;
    const int tp = threadIdx.x % TPG;
    u32*   hTu = (u32*)(smem + tg * GSZ);
    float* scv = smem + tg * GSZ + CHID * HS;
    __shared__ int   sidx[PPB][KNN];
    __shared__ float spi[PPB][3];
    __shared__ int   scnt[PPB];

    const int b = blockIdx.y;
    const int i = blockIdx.x * PPB + tg;

    if (tp < KNN) sidx[tg][tp] = kidx[((size_t)b * N + i) * KNN + tp];
    if (tp == 0)  scnt[tg] = kcnt[b * N + i];
    if (tp < 3)   spi[tg][tp] = pos[((size_t)b * N + i) * 3 + tp];
    __syncthreads();
    const int cnt = scnt[tg];
    const float p0 = spi[tg][0], p1 = spi[tg][1], p2 = spi[tg][2];
    scv[tp] = fmaf(p2, W1p[2 * CHID + tp],
                   fmaf(p1, W1p[CHID + tp], p0 * W1p[tp]));
    __syncthreads();

    const float* ab = a + (size_t)b * N * CHID;
    const float cv = scv[tp];
#pragma unroll
    for (int kq = 0; kq < 8; ++kq) {
        int j0 = sidx[tg][kq * 4 + 0], j1 = sidx[tg][kq * 4 + 1];
        int j2 = sidx[tg][kq * 4 + 2], j3 = sidx[tg][kq * 4 + 3];
        uint4 h;
        h.x = f2tf32(fmaxf(ab[(size_t)j0 * CHID + tp] - cv, 0.f));
        h.y = f2tf32(fmaxf(ab[(size_t)j1 * CHID + tp] - cv, 0.f));
        h.z = f2tf32(fmaxf(ab[(size_t)j2 * CHID + tp] - cv, 0.f));
        h.w = f2tf32(fmaxf(ab[(size_t)j3 * CHID + tp] - cv, 0.f));
        *(uint4*)&hTu[tp * HS + kq * 4] = h;
    }
    __syncthreads();

    const int lane = tp & 31;
    const int w = tp >> 5;
    const int q = lane >> 2, kk = lane & 3;
    const uint4* Wt = (const uint4*)W2T;

    float d[2][4][4];
#pragma unroll
    for (int m = 0; m < 2; ++m)
#pragma unroll
        for (int n = 0; n < 4; ++n)
#pragma unroll
            for (int r = 0; r < 4; ++r) d[m][n][r] = 0.f;

    for (int kt = 0; kt < KT; ++kt) {
        const u32* col0 = hTu + (kt * 8 + kk) * HS;
        const u32* col4 = col0 + 4 * HS;
        u32 A0[4], A1[4];
        A0[0] = col0[q];       A0[1] = col0[q + 8];
        A0[2] = col4[q];       A0[3] = col4[q + 8];
        A1[0] = col0[16 + q];  A1[1] = col0[16 + q + 8];
        A1[2] = col4[16 + q];  A1[3] = col4[16 + q + 8];
        uint4 B0 = Wt[((kt * NW + w) * 32 + lane) * 2 + 0];
        uint4 B1 = Wt[((kt * NW + w) * 32 + lane) * 2 + 1];
        mma_tf32(d[0][0], A0, B0.x, B0.y);
        mma_tf32(d[0][1], A0, B0.z, B0.w);
        mma_tf32(d[0][2], A0, B1.x, B1.y);
        mma_tf32(d[0][3], A0, B1.z, B1.w);
        mma_tf32(d[1][0], A1, B0.x, B0.y);
        mma_tf32(d[1][1], A1, B0.z, B0.w);
        mma_tf32(d[1][2], A1, B1.x, B1.y);
        mma_tf32(d[1][3], A1, B1.z, B1.w);
    }

#pragma unroll
    for (int n = 0; n < 4; ++n) {
        float v0 = -FLT_MAX, v1 = -FLT_MAX;
#pragma unroll
        for (int m = 0; m < 2; ++m) {
            int r0 = m * 16 + q, r1 = r0 + 8;
            if (r0 < cnt) { v0 = fmaxf(v0, d[m][n][0]); v1 = fmaxf(v1, d[m][n][1]); }
            if (r1 < cnt) { v0 = fmaxf(v0, d[m][n][2]); v1 = fmaxf(v1, d[m][n][3]); }
        }
        v0 = fmaxf(v0, __shfl_xor_sync(0xffffffffu, v0, 4));
        v1 = fmaxf(v1, __shfl_xor_sync(0xffffffffu, v1, 4));
        v0 = fmaxf(v0, __shfl_xor_sync(0xffffffffu, v0, 8));
        v1 = fmaxf(v1, __shfl_xor_sync(0xffffffffu, v1, 8));
        v0 = fmaxf(v0, __shfl_xor_sync(0xffffffffu, v0, 16));
        v1 = fmaxf(v1, __shfl_xor_sync(0xffffffffu, v1, 16));
        if (lane < 4) {
            int c = w * 32 + n * 8 + lane * 2;
            float o0 = (cnt > 0) ? fmaxf(v0 + b2[c], 0.f) : 0.f;
            float o1 = (cnt > 0) ? fmaxf(v1 + b2[c + 1], 0.f) : 0.f;
            xout[((size_t)b * N + i) * COUT + c]     = o0;
            xout[((size_t)b * N + i) * COUT + c + 1] = o1;
        }
    }
}

// ---------------- head ----------------
__global__ void head_kernel(const float* __restrict__ x3,
                            const float* __restrict__ Wc1, const float* __restrict__ bc1,
                            const float* __restrict__ Wc2, const float* __restrict__ bc2,
                            const float* __restrict__ Wc3, const float* __restrict__ bc3,
                            const float* __restrict__ Wd1, const float* __restrict__ bd1,
                            const float* __restrict__ Wd2, const float* __restrict__ bd2,
                            float* __restrict__ out)
{
    __shared__ float sf[256], sh[256], sh2[256], slog[40], sd[2];
    const int b = blockIdx.x, t = threadIdx.x;

    float m = -FLT_MAX;
    for (int n = 0; n < N3; ++n)
        m = fmaxf(m, x3[((size_t)b * N3 + n) * 256 + t]);
    sf[t] = m;
    __syncthreads();

    float a = bc1[t];
    for (int c = 0; c < 256; ++c) a = fmaf(sf[c], Wc1[c * 256 + t], a);
    sh[t] = fmaxf(a, 0.f);
    __syncthreads();

    a = bc2[t];
    for (int c = 0; c < 256; ++c) a = fmaf(sh[c], Wc2[c * 256 + t], a);
    sh2[t] = fmaxf(a, 0.f);
    __syncthreads();

    if (t < 40) {
        float l = bc3[t];
        for (int c = 0; c < 256; ++c) l = fmaf(sh2[c], Wc3[c * 40 + t], l);
        slog[t] = l;
    }
    float a2 = bd1[t];
    for (int c = 0; c < 256; ++c) a2 = fmaf(sf[c], Wd1[c * 256 + t], a2);
    a2 = fmaxf(a2, 0.f);
    __syncthreads();
    sh[t] = a2;
    __syncthreads();
    if (t < 2) {
        float l = bd2[t];
        for (int c = 0; c < 256; ++c) l = fmaf(sh[c], Wd2[c * 2 + t], l);
        sd[t] = l;
    }
    __syncthreads();

    if (t < 40) {
        float mx = -FLT_MAX;
        for (int j = 0; j < 40; ++j) mx = fmaxf(mx, slog[j]);
        float se = 0.f;
        for (int j = 0; j < 40; ++j) se += expf(slog[j] - mx);
        out[b * 40 + t] = slog[t] - mx - logf(se);
    }
    if (t < 2) {
        float mx = fmaxf(sd[0], sd[1]);
        float se = expf(sd[0] - mx) + expf(sd[1] - mx);
        out[NB * 40 + b * 2 + t] = sd[t] - mx - logf(se);
    }
}

// ---------------- stream/event singletons ----------------
static cudaStream_t g_s2;
static cudaEvent_t g_evA, g_evP2, g_evP3;
static bool g_init = []() {
    cudaStreamCreateWithFlags(&g_s2, cudaStreamNonBlocking);
    cudaEventCreateWithFlags(&g_evA,  cudaEventDisableTiming);
    cudaEventCreateWithFlags(&g_evP2, cudaEventDisableTiming);
    cudaEventCreateWithFlags(&g_evP3, cudaEventDisableTiming);
    return true;
}();

// ---------------- launch ----------------
extern "C" void kernel_launch(void* const* d_in, const int* in_sizes, int n_in,
                              void* d_out, int out_size)
{
    const float* pos = (const float*)d_in[0];
    const float* W1a = (const float*)d_in[1];  const float* b1a = (const float*)d_in[2];
    const float* W1b = (const float*)d_in[3];  const float* b1b = (const float*)d_in[4];
    const float* W2a = (const float*)d_in[5];  const float* b2a = (const float*)d_in[6];
    const float* W2b = (const float*)d_in[7];  const float* b2b = (const float*)d_in[8];
    const float* W3a = (const float*)d_in[9];  const float* b3a = (const float*)d_in[10];
    const float* W3b = (const float*)d_in[11]; const float* b3b = (const float*)d_in[12];
    const float* Wc1 = (const float*)d_in[13]; const float* bc1 = (const float*)d_in[14];
    const float* Wc2 = (const float*)d_in[15]; const float* bc2 = (const float*)d_in[16];
    const float* Wc3 = (const float*)d_in[17]; const float* bc3 = (const float*)d_in[18];
    const float* Wd1 = (const float*)d_in[19]; const float* bd1 = (const float*)d_in[20];
    const float* Wd2 = (const float*)d_in[21]; const float* bd2 = (const float*)d_in[22];
    float* out = (float*)d_out;

    void *p_idx1, *p_cnt1, *p_a1, *p_x1, *p_fi1, *p_pos2, *p_x2g, *p_a2,
         *p_idx2, *p_cnt2, *p_x2, *p_fi2, *p_pos3, *p_x3g, *p_a3,
         *p_idx3, *p_cnt3, *p_x3, *p_pm1, *p_pm2, *p_pm3,
         *p_w1, *p_w2, *p_w3;
    cudaGetSymbolAddress(&p_idx1, g_idx1);
    cudaGetSymbolAddress(&p_cnt1, g_cnt1);
    cudaGetSymbolAddress(&p_a1,   g_a1);
    cudaGetSymbolAddress(&p_x1,   g_x1);
    cudaGetSymbolAddress(&p_fi1,  g_fi1);
    cudaGetSymbolAddress(&p_pos2, g_pos2);
    cudaGetSymbolAddress(&p_x2g,  g_x2g);
    cudaGetSymbolAddress(&p_a2,   g_a2);
    cudaGetSymbolAddress(&p_idx2, g_idx2);
    cudaGetSymbolAddress(&p_cnt2, g_cnt2);
    cudaGetSymbolAddress(&p_x2,   g_x2);
    cudaGetSymbolAddress(&p_fi2,  g_fi2);
    cudaGetSymbolAddress(&p_pos3, g_pos3);
    cudaGetSymbolAddress(&p_x3g,  g_x3g);
    cudaGetSymbolAddress(&p_a3,   g_a3);
    cudaGetSymbolAddress(&p_idx3, g_idx3);
    cudaGetSymbolAddress(&p_cnt3, g_cnt3);
    cudaGetSymbolAddress(&p_x3,   g_x3);
    cudaGetSymbolAddress(&p_pm1,  g_perm1);
    cudaGetSymbolAddress(&p_pm2,  g_perm2);
    cudaGetSymbolAddress(&p_pm3,  g_perm3);
    cudaGetSymbolAddress(&p_w1,   g_w2t1);
    cudaGetSymbolAddress(&p_w2,   g_w2t2);
    cudaGetSymbolAddress(&p_w3,   g_w2t3);

    const int smFps1 = N1 * 12 + 256;
    const int smFps2 = N2 * 12 + 256;
    const int smKnn  = 512 * 16;
    const int shc1 = 4 * (64 * 40 + 64)  * 4;
    const int shc2 = 2 * (128 * 40 + 128) * 4;
    const int shc3 = 1 * (256 * 40 + 256) * 4;
    cudaFuncSetAttribute(fps_kernel<8>,
                         cudaFuncAttributeMaxDynamicSharedMemorySize, 50176);

    const float r1 = 0.2f, r2 = 0.4f, r3 = 1.0f;

    // ======== fork: FPS spine on s2 (needs only pos) ======================
    cudaEventRecord(g_evA, 0);
    cudaStreamWaitEvent(g_s2, g_evA, 0);
    fps_kernel<8><<<NB, 512, smFps1, g_s2>>>(pos, N2, (int*)p_fi1);
    posgather_kernel<<<(NB * N2 * 3 + 255) / 256, 256, 0, g_s2>>>(
        pos, (int*)p_fi1, (float*)p_pos2, N1, N2);
    cudaEventRecord(g_evP2, g_s2);
    fps_kernel<4><<<NB, 512, smFps2, g_s2>>>((float*)p_pos2, N3, (int*)p_fi2);
    posgather_kernel<<<(NB * N3 * 3 + 255) / 256, 256, 0, g_s2>>>(
        (float*)p_pos2, (int*)p_fi2, (float*)p_pos3, N2, N3);
    cudaEventRecord(g_evP3, g_s2);

    // ======== main stream: all compute ====================================
    // level 1
    binsort_kernel<5><<<NB, 256>>>(pos, N1, (int*)p_pm1);
    w2t_pre_kernel<64, 64><<<16, 256>>>(W1b, (u32*)p_w1);
    w2t_pre_kernel<128, 128><<<64, 256>>>(W2b, (u32*)p_w2);
    w2t_pre_kernel<256, 256><<<256, 256>>>(W3b, (u32*)p_w3);
    node_gemm_kernel<0, 64, 128><<<(NB * N1) / 128, 256>>>(
        nullptr, pos, W1a, b1a, (float*)p_a1);
    knn_kernel<<<(N1 / 512) * NB, 512, smKnn>>>(
        pos, N1, r1 * r1, (int*)p_idx1, (int*)p_cnt1, (int*)p_pm1);
    conv_mma_kernel<64, 64><<<dim3(N1 / 4, NB), 256, shc1>>>(
        (float*)p_a1, pos, (int*)p_idx1, (int*)p_cnt1,
        W1a, (u32*)p_w1, b1b, (float*)p_x1, N1);

    // level 2 (needs pos2/fi1 from s2)
    cudaStreamWaitEvent(0, g_evP2, 0);
    binsort_kernel<4><<<NB, 256>>>((float*)p_pos2, N2, (int*)p_pm2);
    knn_kernel<<<(N2 / 512) * NB, 512, smKnn>>>(
        (float*)p_pos2, N2, r2 * r2, (int*)p_idx2, (int*)p_cnt2, (int*)p_pm2);
    xgather_kernel<<<512, 256>>>((float*)p_x1, (int*)p_fi1,
                                 (float*)p_x2g, N1, N2, 64);
    node_gemm_kernel<64, 128, 64><<<(NB * N2) / 64, 256>>>(
        (float*)p_x2g, (float*)p_pos2, W2a, b2a, (float*)p_a2);
    conv_mma_kernel<128, 128><<<dim3(N2 / 2, NB), 256, shc2>>>(
        (float*)p_a2, (float*)p_pos2, (int*)p_idx2, (int*)p_cnt2,
        W2a + 64 * 128, (u32*)p_w2, b2b, (float*)p_x2, N2);

    // level 3 (needs pos3/fi2 from s2)
    cudaStreamWaitEvent(0, g_evP3, 0);
    binsort_kernel<4><<<NB, 256>>>((float*)p_pos3, N3, (int*)p_pm3);
    knn_kernel<<<(N3 / 512) * NB, 512, smKnn>>>(
        (float*)p_pos3, N3, r3 * r3, (int*)p_idx3, (int*)p_cnt3, (int*)p_pm3);
    xgather_kernel<<<512, 256>>>((float*)p_x2, (int*)p_fi2,
                                 (float*)p_x3g, N2, N3, 128);
    node_gemm_kernel<128, 256, 32><<<(NB * N3) / 32, 256>>>(
        (float*)p_x3g, (float*)p_pos3, W3a, b3a, (float*)p_a3);
    conv_mma_kernel<256, 256><<<dim3(N3, NB), 256, shc3>>>(
        (float*)p_a3, (float*)p_pos3, (int*)p_idx3, (int*)p_cnt3,
        W3a + 128 * 256, (u32*)p_w3, b3b, (float*)p_x3, N3);

    // head
    head_kernel<<<NB, 256>>>((float*)p_x3, Wc1, bc1, Wc2, bc2, Wc3, bc3,
                             Wd1, bd1, Wd2, bd2, out);

    (void)in_sizes; (void)n_in; (void)out_size; (void)g_init;
}

// round 16
// speedup vs baseline: 1.5648x; 1.5648x over previous
#include <cuda_runtime.h>
#include <math.h>
#include <float.h>

typedef unsigned int u32;

static constexpr int NB = 8, N1 = 4096, N2 = 2048, N3 = 512, KNN = 32;

// ---------------- scratch ----------------
__device__ int   g_idx1[NB * N1 * KNN];
__device__ int   g_cnt1[NB * N1];
__device__ float g_a1  [NB * N1 * 64];
__device__ float g_x1  [NB * N1 * 64];
__device__ int   g_fi1 [NB * N2];
__device__ float g_pos2[NB * N2 * 3];
__device__ float g_x2g [NB * N2 * 64];
__device__ float g_a2  [NB * N2 * 128];
__device__ int   g_idx2[NB * N2 * KNN];
__device__ int   g_cnt2[NB * N2];
__device__ float g_x2  [NB * N2 * 128];
__device__ int   g_fi2 [NB * N3];
__device__ float g_pos3[NB * N3 * 3];
__device__ float g_x3g [NB * N3 * 128];
__device__ float g_a3  [NB * N3 * 256];
__device__ int   g_idx3[NB * N3 * KNN];
__device__ int   g_cnt3[NB * N3];
__device__ float g_x3  [NB * N3 * 256];
__device__ int   g_perm3[NB * N3];
__device__ u32   g_w2t1[4096];
__device__ u32   g_w2t2[16384];
__device__ u32   g_w2t3[65536];
// binned-KNN structures (levels 1-2)
__device__ float4 g_ps1[NB * N1];
__device__ int    g_si1[NB * N1];
__device__ int    g_bo1[NB * 126];      // 5^3 + 1
__device__ float4 g_ps2[NB * N2];
__device__ int    g_si2[NB * N2];
__device__ int    g_bo2[NB * 65];       // 4^3 + 1

// ---------------- tf32 helpers ----------------
__device__ __forceinline__ u32 f2tf32(float f) {
    u32 r; asm("cvt.rna.tf32.f32 %0,%1;" : "=r"(r) : "f"(f)); return r;
}
__device__ __forceinline__ void mma_tf32(float* d, const u32* A, u32 b0, u32 b1) {
    asm("mma.sync.aligned.m16n8k8.row.col.f32.tf32.tf32.f32 "
        "{%0,%1,%2,%3},{%4,%5,%6,%7},{%8,%9},{%0,%1,%2,%3};"
        : "+f"(d[0]), "+f"(d[1]), "+f"(d[2]), "+f"(d[3])
        : "r"(A[0]), "r"(A[1]), "r"(A[2]), "r"(A[3]), "r"(b0), "r"(b1));
}

// ---------------- W2 -> tf32 fragment-major precompute ----------------
template <int CHID, int COUT>
__global__ void __launch_bounds__(256)
w2t_pre_kernel(const float* __restrict__ W2, u32* __restrict__ W2T)
{
    constexpr int NW = COUT / 32;
    int tid = blockIdx.x * 256 + threadIdx.x;
    int lane8 = tid & 255;
    int lane = lane8 >> 3, n = (lane8 & 7) >> 1, r = lane8 & 1;
    int rest = tid >> 8;
    int w = rest % NW, kt = rest / NW;
    int k = kt * 8 + (lane & 3) + r * 4;
    int c = w * 32 + n * 8 + (lane >> 2);
    W2T[tid] = f2tf32(W2[k * COUT + c]);
}

// ---------------- classic binsort (perm only; level 3) ----------------
template <int NBIN>
__global__ void __launch_bounds__(256)
binsort_kernel(const float* __restrict__ pos, int N, int* __restrict__ perm)
{
    constexpr int B3 = NBIN * NBIN * NBIN;
    __shared__ int hist[B3];
    __shared__ int offs[B3];
    const int b = blockIdx.x, t = threadIdx.x;
    const float* pb = pos + (size_t)b * N * 3;

    for (int e = t; e < B3; e += 256) hist[e] = 0;
    __syncthreads();
    for (int i = t; i < N; i += 256) {
        int ix = min(NBIN - 1, max(0, (int)(pb[i * 3 + 0] * NBIN)));
        int iy = min(NBIN - 1, max(0, (int)(pb[i * 3 + 1] * NBIN)));
        int iz = min(NBIN - 1, max(0, (int)(pb[i * 3 + 2] * NBIN)));
        atomicAdd(&hist[(ix * NBIN + iy) * NBIN + iz], 1);
    }
    __syncthreads();
    if (t == 0) {
        int acc = 0;
        for (int k = 0; k < B3; ++k) { offs[k] = acc; acc += hist[k]; }
    }
    __syncthreads();
    for (int e = t; e < B3; e += 256) hist[e] = 0;
    __syncthreads();
    for (int i = t; i < N; i += 256) {
        int ix = min(NBIN - 1, max(0, (int)(pb[i * 3 + 0] * NBIN)));
        int iy = min(NBIN - 1, max(0, (int)(pb[i * 3 + 1] * NBIN)));
        int iz = min(NBIN - 1, max(0, (int)(pb[i * 3 + 2] * NBIN)));
        int key = (ix * NBIN + iy) * NBIN + iz;
        int r = offs[key] + atomicAdd(&hist[key], 1);
        perm[b * N + r] = i;
    }
}

// ---------------- extended binsort: sorted candidates + offsets ----------
template <int NBIN>
__global__ void __launch_bounds__(256)
binsort2_kernel(const float* __restrict__ pos, int N,
                float4* __restrict__ ps, int* __restrict__ sidx,
                int* __restrict__ boff)
{
    constexpr int B3 = NBIN * NBIN * NBIN;
    __shared__ int hist[B3];
    __shared__ int offs[B3];
    const int b = blockIdx.x, t = threadIdx.x;
    const float* pb = pos + (size_t)b * N * 3;

    for (int e = t; e < B3; e += 256) hist[e] = 0;
    __syncthreads();
    for (int i = t; i < N; i += 256) {
        int ix = min(NBIN - 1, max(0, (int)(pb[i * 3 + 0] * NBIN)));
        int iy = min(NBIN - 1, max(0, (int)(pb[i * 3 + 1] * NBIN)));
        int iz = min(NBIN - 1, max(0, (int)(pb[i * 3 + 2] * NBIN)));
        atomicAdd(&hist[(ix * NBIN + iy) * NBIN + iz], 1);
    }
    __syncthreads();
    if (t == 0) {
        int acc = 0;
        for (int k = 0; k < B3; ++k) { offs[k] = acc; acc += hist[k]; }
    }
    __syncthreads();
    for (int e = t; e < B3; e += 256) boff[b * (B3 + 1) + e] = offs[e];
    if (t == 0) boff[b * (B3 + 1) + B3] = N;
    for (int e = t; e < B3; e += 256) hist[e] = 0;
    __syncthreads();
    for (int i = t; i < N; i += 256) {
        float x = pb[i * 3 + 0], y = pb[i * 3 + 1], z = pb[i * 3 + 2];
        int ix = min(NBIN - 1, max(0, (int)(x * NBIN)));
        int iy = min(NBIN - 1, max(0, (int)(y * NBIN)));
        int iz = min(NBIN - 1, max(0, (int)(z * NBIN)));
        int key = (ix * NBIN + iy) * NBIN + iz;
        int r = offs[key] + atomicAdd(&hist[key], 1);
        float sq = __fadd_rn(__fadd_rn(__fmul_rn(x, x), __fmul_rn(y, y)),
                             __fmul_rn(z, z));
        ps[(size_t)b * N + r] = make_float4(x, y, z, sq);
        sidx[b * N + r] = i;
    }
}

// ---------------- per-node a_j = [x_j, pos_j] @ W1 + b1 ----------------
template <int CINX, int CHID>
__global__ void __launch_bounds__(256)
node_pre_kernel(const float* __restrict__ x, const float* __restrict__ pos,
                const float* __restrict__ W1, const float* __restrict__ b1,
                float* __restrict__ a, int nNodes)
{
    int tid = blockIdx.x * 256 + threadIdx.x;
    if (tid >= nNodes * CHID) return;
    int node = tid / CHID, c = tid - node * CHID;
    float acc = b1[c];
    if (CINX > 0) {
        const float* xr = x + (size_t)node * CINX;
#pragma unroll 4
        for (int f = 0; f < CINX; ++f)
            acc = fmaf(xr[f], W1[f * CHID + c], acc);
    }
    const float* pr = pos + (size_t)node * 3;
    acc = fmaf(pr[0], W1[(CINX + 0) * CHID + c], acc);
    acc = fmaf(pr[1], W1[(CINX + 1) * CHID + c], acc);
    acc = fmaf(pr[2], W1[(CINX + 2) * CHID + c], acc);
    a[tid] = acc;
}

// ---------------- binned KNN (levels 1-2): shell-ordered candidate scan ---
template <int NBIN, int S>
__global__ void __launch_bounds__(512, 1)
knnb_kernel(const float4* __restrict__ ps, const int* __restrict__ sidx,
            const int* __restrict__ boff, int N, float r2v,
            int* __restrict__ oidx, int* __restrict__ ocnt)
{
    constexpr int B3 = NBIN * NBIN * NBIN;
    const int b = blockIdx.x % NB, qb = blockIdx.x / NB;
    const float4* P = ps + (size_t)b * N;
    const int* SI = sidx + (size_t)b * N;
    const int* BO = boff + b * (B3 + 1);
    const int rank = qb * 512 + threadIdx.x;

    float4 qv = P[rank];
    const int qi = SI[rank];
    const float xi = qv.x, yi = qv.y, zi = qv.z, sqi = qv.w;
    const float m2x = -2.f * xi, m2y = -2.f * yi, m2z = -2.f * zi;
    const int bx = min(NBIN - 1, max(0, (int)(xi * NBIN)));
    const int by = min(NBIN - 1, max(0, (int)(yi * NBIN)));
    const int bz = min(NBIN - 1, max(0, (int)(zi * NBIN)));

    float bd[KNN];
    int   bi_[KNN];
#pragma unroll
    for (int k = 0; k < KNN; ++k) { bd[k] = FLT_MAX; bi_[k] = 0; }
    float worst = FLT_MAX;

    for (int s = 0; s <= S; ++s) {
        for (int dx = -s; dx <= s; ++dx) {
            int nx = bx + dx;
            if (nx < 0 || nx >= NBIN) continue;
            int adx = dx < 0 ? -dx : dx;
            for (int dy = -s; dy <= s; ++dy) {
                int ny = by + dy;
                if (ny < 0 || ny >= NBIN) continue;
                int ady = dy < 0 ? -dy : dy;
                for (int dz = -s; dz <= s; ++dz) {
                    int nz = bz + dz;
                    if (nz < 0 || nz >= NBIN) continue;
                    int adz = dz < 0 ? -dz : dz;
                    int cheb = max(adx, max(ady, adz));
                    if (cheb != s) continue;
                    int key = (nx * NBIN + ny) * NBIN + nz;
                    int rEnd = BO[key + 1];
                    for (int r = BO[key]; r < rEnd; ++r) {
                        float4 c = P[r];
                        float d2 = sqi + fmaf(m2x, c.x,
                                       fmaf(m2y, c.y, fmaf(m2z, c.z, c.w)));
                        if (d2 <= r2v && d2 < worst) {
                            int j = SI[r];
                            if (j != qi) {
#pragma unroll
                                for (int k = KNN - 1; k > 0; --k) {
                                    if (bd[k - 1] > d2)  { bd[k] = bd[k - 1]; bi_[k] = bi_[k - 1]; }
                                    else if (bd[k] > d2) { bd[k] = d2;        bi_[k] = j; }
                                }
                                if (bd[0] > d2)          { bd[0] = d2;        bi_[0] = j; }
                                worst = bd[KNN - 1];
                            }
                        }
                    }
                }
            }
        }
    }
    int cnt = 0;
#pragma unroll
    for (int k = 0; k < KNN; ++k) cnt += (bd[k] <= r2v) ? 1 : 0;
    ocnt[b * N + qi] = cnt;                       // FIX: batch offset
    const int base = (b * N + qi) * KNN;          // FIX: batch offset
#pragma unroll
    for (int k = 0; k < KNN; ++k) oidx[base + k] = bi_[k];
}

// ---------------- classic tile KNN (level 3) ----------------
__device__ void knn_dev(const float* __restrict__ pb, int N, float r2v,
                        int* __restrict__ oidx, int* __restrict__ ocnt,
                        int qb, const int* __restrict__ perm, float4* sj)
{
    const int t = threadIdx.x;
    const int i = perm[qb * 512 + t];
    const float xi = pb[i * 3 + 0], yi = pb[i * 3 + 1], zi = pb[i * 3 + 2];
    const float sqi = __fadd_rn(__fadd_rn(__fmul_rn(xi, xi), __fmul_rn(yi, yi)),
                                __fmul_rn(zi, zi));
    const float m2x = -2.f * xi, m2y = -2.f * yi, m2z = -2.f * zi;

    float bd[KNN];
    int   bi_[KNN];
#pragma unroll
    for (int k = 0; k < KNN; ++k) { bd[k] = FLT_MAX; bi_[k] = 0; }
    float worst = FLT_MAX;

    for (int t0 = 0; t0 < N; t0 += 512) {
        __syncthreads();
        {
            int j = t0 + t;
            float x = pb[j * 3 + 0], y = pb[j * 3 + 1], z = pb[j * 3 + 2];
            float sq = __fadd_rn(__fadd_rn(__fmul_rn(x, x), __fmul_rn(y, y)),
                                 __fmul_rn(z, z));
            sj[t] = make_float4(x, y, z, sq);
        }
        __syncthreads();
#pragma unroll 2
        for (int jj = 0; jj < 512; ++jj) {
            float4 q = sj[jj];
            float d2 = sqi + fmaf(m2x, q.x, fmaf(m2y, q.y, fmaf(m2z, q.z, q.w)));
            int j = t0 + jj;
            if (d2 <= r2v && d2 < worst && j != i) {
#pragma unroll
                for (int k = KNN - 1; k > 0; --k) {
                    if (bd[k - 1] > d2)  { bd[k] = bd[k - 1]; bi_[k] = bi_[k - 1]; }
                    else if (bd[k] > d2) { bd[k] = d2;        bi_[k] = j; }
                }
                if (bd[0] > d2)          { bd[0] = d2;        bi_[0] = j; }
                worst = bd[KNN - 1];
            }
        }
    }
    int cnt = 0;
#pragma unroll
    for (int k = 0; k < KNN; ++k) cnt += (bd[k] <= r2v) ? 1 : 0;
    ocnt[i] = cnt;
    const int base = i * KNN;
#pragma unroll
    for (int k = 0; k < KNN; ++k) oidx[base + k] = bi_[k];
}

__global__ void __launch_bounds__(512, 1)
knn_kernel(const float* __restrict__ pos, int N, float r2v,
           int* __restrict__ oidx, int* __restrict__ ocnt,
           const int* __restrict__ perm)
{
    extern __shared__ char sm[];
    int b = blockIdx.x % NB, qb = blockIdx.x / NB;
    knn_dev(pos + (size_t)b * N * 3, N, r2v,
            oidx + (size_t)b * N * KNN, ocnt + b * N, qb,
            perm + b * N, (float4*)sm);
}

// ---------------- FPS (512 threads) ----------------
template <int P>
__global__ void __launch_bounds__(512, 1)
fps_kernel(const float* __restrict__ pos, int nS, int* __restrict__ fi)
{
    extern __shared__ char sm[];
    float* smf = (float*)sm;
    const int N = P * 512;
    const float* pb = pos + (size_t)blockIdx.x * N * 3;
    int* out = fi + blockIdx.x * nS;
    float* spos = smf;
    u32*  svb = (u32*)(smf + N * 3);
    int*  si  = (int*)(svb + 32);
    const int t = threadIdx.x, w = t >> 5, l = t & 31;

    for (int e = t; e < N * 3; e += 512) spos[e] = pb[e];
    __syncthreads();

    float px[P], py[P], pz[P], mind[P];
    const float x0 = spos[0], y0 = spos[1], z0 = spos[2];
    float bv = -1.f; int bidx = 0x7fffffff;
#pragma unroll
    for (int p = 0; p < P; ++p) {
        int i = t + p * 512;
        px[p] = spos[i * 3 + 0]; py[p] = spos[i * 3 + 1]; pz[p] = spos[i * 3 + 2];
        float dx = px[p] - x0, dy = py[p] - y0, dz = pz[p] - z0;
        mind[p] = __fadd_rn(__fadd_rn(__fmul_rn(dx, dx), __fmul_rn(dy, dy)),
                            __fmul_rn(dz, dz));
        if (mind[p] > bv) { bv = mind[p]; bidx = i; }
    }
    if (t == 0) out[0] = 0;

    int par = 0;
    for (int s = 1; s < nS; ++s) {
        u32 vb = __float_as_uint(bv);
        u32 m  = __reduce_max_sync(0xffffffffu, vb);
        u32 cand = (vb == m) ? (u32)bidx : 0xffffffffu;
        u32 wi = __reduce_min_sync(0xffffffffu, cand);
        if (l == 0) { svb[par * 16 + w] = m; si[par * 16 + w] = (int)wi; }
        __syncthreads();
        u32 v2 = (l < 16) ? svb[par * 16 + l] : 0u;
        u32 i2 = (l < 16) ? (u32)si[par * 16 + l] : 0xffffffffu;
        u32 m2 = __reduce_max_sync(0xffffffffu, v2);
        u32 c2 = (v2 == m2 && l < 16) ? i2 : 0xffffffffu;
        u32 gi = __reduce_min_sync(0xffffffffu, c2);
        if (t == 0) out[s] = (int)gi;
        const float cx = spos[gi * 3 + 0];
        const float cy = spos[gi * 3 + 1];
        const float cz = spos[gi * 3 + 2];
        par ^= 1;
        bv = -1.f; bidx = 0x7fffffff;
#pragma unroll
        for (int p = 0; p < P; ++p) {
            float dx = px[p] - cx, dy = py[p] - cy, dz = pz[p] - cz;
            float d = __fadd_rn(__fadd_rn(__fmul_rn(dx, dx), __fmul_rn(dy, dy)),
                                __fmul_rn(dz, dz));
            mind[p] = fminf(mind[p], d);
            if (mind[p] > bv) { bv = mind[p]; bidx = t + p * 512; }
        }
    }
}

// ---------------- pos-only gather ----------------
__global__ void posgather_kernel(const float* __restrict__ posin,
                                 const int* __restrict__ fi,
                                 float* __restrict__ poso, int Nin, int Nout)
{
    const int tid = blockIdx.x * blockDim.x + threadIdx.x;
    const int tot = NB * Nout * 3;
    if (tid >= tot) return;
    int d = tid % 3, m = (tid / 3) % Nout, b = tid / (3 * Nout);
    int j = fi[b * Nout + m];
    poso[tid] = posin[((size_t)b * Nin + j) * 3 + d];
}

// ---------------- feature gather ----------------
__global__ void xgather_kernel(const float* __restrict__ xin,
                               const int* __restrict__ fi,
                               float* __restrict__ xo, int Nin, int Nout, int C)
{
    const int tid = blockIdx.x * blockDim.x + threadIdx.x;
    const int stride = gridDim.x * blockDim.x;
    const int tot = NB * Nout * C;
    for (int e = tid; e < tot; e += stride) {
        int c = e % C, m = (e / C) % Nout, b = e / (C * Nout);
        int j = fi[b * Nout + m];
        xo[e] = xin[((size_t)b * Nin + j) * C + c];
    }
}

// ---------------- PointNetConv on tensor cores ----------------
template <int CHID, int COUT>
__global__ void __launch_bounds__(256)
conv_mma_kernel(const float* __restrict__ a, const float* __restrict__ pos,
                const int* __restrict__ kidx, const int* __restrict__ kcnt,
                const float* __restrict__ W1p, const u32* __restrict__ W2T,
                const float* __restrict__ b2, float* __restrict__ xout, int N)
{
    constexpr int NW  = COUT / 32;
    constexpr int TPG = COUT;
    constexpr int PPB = 256 / TPG;
    constexpr int KT  = CHID / 8;
    constexpr int HS  = 40;
    constexpr int GSZ = CHID * HS + CHID;
    extern __shared__ char sm[];
    float* smem = (float*)sm;
    const int tg = threadIdx.x / TPG;
    const int tp = threadIdx.x % TPG;
    u32*   hTu = (u32*)(smem + tg * GSZ);
    float* scv = smem + tg * GSZ + CHID * HS;
    __shared__ int   sidx[PPB][KNN];
    __shared__ float spi[PPB][3];
    __shared__ int   scnt[PPB];

    const int b = blockIdx.y;
    const int i = blockIdx.x * PPB + tg;

    if (tp < KNN) sidx[tg][tp] = kidx[((size_t)b * N + i) * KNN + tp];
    if (tp == 0)  scnt[tg] = kcnt[b * N + i];
    if (tp < 3)   spi[tg][tp] = pos[((size_t)b * N + i) * 3 + tp];
    __syncthreads();
    const int cnt = scnt[tg];
    const float p0 = spi[tg][0], p1 = spi[tg][1], p2 = spi[tg][2];
    scv[tp] = fmaf(p2, W1p[2 * CHID + tp],
                   fmaf(p1, W1p[CHID + tp], p0 * W1p[tp]));
    __syncthreads();

    const float* ab = a + (size_t)b * N * CHID;
    const float cv = scv[tp];
#pragma unroll
    for (int kq = 0; kq < 8; ++kq) {
        int j0 = sidx[tg][kq * 4 + 0], j1 = sidx[tg][kq * 4 + 1];
        int j2 = sidx[tg][kq * 4 + 2], j3 = sidx[tg][kq * 4 + 3];
        uint4 h;
        h.x = f2tf32(fmaxf(ab[(size_t)j0 * CHID + tp] - cv, 0.f));
        h.y = f2tf32(fmaxf(ab[(size_t)j1 * CHID + tp] - cv, 0.f));
        h.z = f2tf32(fmaxf(ab[(size_t)j2 * CHID + tp] - cv, 0.f));
        h.w = f2tf32(fmaxf(ab[(size_t)j3 * CHID + tp] - cv, 0.f));
        *(uint4*)&hTu[tp * HS + kq * 4] = h;
    }
    __syncthreads();

    const int lane = tp & 31;
    const int w = tp >> 5;
    const int q = lane >> 2, kk = lane & 3;
    const uint4* Wt = (const uint4*)W2T;

    float d[2][4][4];
#pragma unroll
    for (int m = 0; m < 2; ++m)
#pragma unroll
        for (int n = 0; n < 4; ++n)
#pragma unroll
            for (int r = 0; r < 4; ++r) d[m][n][r] = 0.f;

    for (int kt = 0; kt < KT; ++kt) {
        const u32* col0 = hTu + (kt * 8 + kk) * HS;
        const u32* col4 = col0 + 4 * HS;
        u32 A0[4], A1[4];
        A0[0] = col0[q];       A0[1] = col0[q + 8];
        A0[2] = col4[q];       A0[3] = col4[q + 8];
        A1[0] = col0[16 + q];  A1[1] = col0[16 + q + 8];
        A1[2] = col4[16 + q];  A1[3] = col4[16 + q + 8];
        uint4 B0 = Wt[((kt * NW + w) * 32 + lane) * 2 + 0];
        uint4 B1 = Wt[((kt * NW + w) * 32 + lane) * 2 + 1];
        mma_tf32(d[0][0], A0, B0.x, B0.y);
        mma_tf32(d[0][1], A0, B0.z, B0.w);
        mma_tf32(d[0][2], A0, B1.x, B1.y);
        mma_tf32(d[0][3], A0, B1.z, B1.w);
        mma_tf32(d[1][0], A1, B0.x, B0.y);
        mma_tf32(d[1][1], A1, B0.z, B0.w);
        mma_tf32(d[1][2], A1, B1.x, B1.y);
        mma_tf32(d[1][3], A1, B1.z, B1.w);
    }

#pragma unroll
    for (int n = 0; n < 4; ++n) {
        float v0 = -FLT_MAX, v1 = -FLT_MAX;
#pragma unroll
        for (int m = 0; m < 2; ++m) {
            int r0 = m * 16 + q, r1 = r0 + 8;
            if (r0 < cnt) { v0 = fmaxf(v0, d[m][n][0]); v1 = fmaxf(v1, d[m][n][1]); }
            if (r1 < cnt) { v0 = fmaxf(v0, d[m][n][2]); v1 = fmaxf(v1, d[m][n][3]); }
        }
        v0 = fmaxf(v0, __shfl_xor_sync(0xffffffffu, v0, 4));
        v1 = fmaxf(v1, __shfl_xor_sync(0xffffffffu, v1, 4));
        v0 = fmaxf(v0, __shfl_xor_sync(0xffffffffu, v0, 8));
        v1 = fmaxf(v1, __shfl_xor_sync(0xffffffffu, v1, 8));
        v0 = fmaxf(v0, __shfl_xor_sync(0xffffffffu, v0, 16));
        v1 = fmaxf(v1, __shfl_xor_sync(0xffffffffu, v1, 16));
        if (lane < 4) {
            int c = w * 32 + n * 8 + lane * 2;
            float o0 = (cnt > 0) ? fmaxf(v0 + b2[c], 0.f) : 0.f;
            float o1 = (cnt > 0) ? fmaxf(v1 + b2[c + 1], 0.f) : 0.f;
            xout[((size_t)b * N + i) * COUT + c]     = o0;
            xout[((size_t)b * N + i) * COUT + c + 1] = o1;
        }
    }
}

// ---------------- head ----------------
__global__ void head_kernel(const float* __restrict__ x3,
                            const float* __restrict__ Wc1, const float* __restrict__ bc1,
                            const float* __restrict__ Wc2, const float* __restrict__ bc2,
                            const float* __restrict__ Wc3, const float* __restrict__ bc3,
                            const float* __restrict__ Wd1, const float* __restrict__ bd1,
                            const float* __restrict__ Wd2, const float* __restrict__ bd2,
                            float* __restrict__ out)
{
    __shared__ float sf[256], sh[256], sh2[256], slog[40], sd[2];
    const int b = blockIdx.x, t = threadIdx.x;

    float m = -FLT_MAX;
    for (int n = 0; n < N3; ++n)
        m = fmaxf(m, x3[((size_t)b * N3 + n) * 256 + t]);
    sf[t] = m;
    __syncthreads();

    float a = bc1[t];
    for (int c = 0; c < 256; ++c) a = fmaf(sf[c], Wc1[c * 256 + t], a);
    sh[t] = fmaxf(a, 0.f);
    __syncthreads();

    a = bc2[t];
    for (int c = 0; c < 256; ++c) a = fmaf(sh[c], Wc2[c * 256 + t], a);
    sh2[t] = fmaxf(a, 0.f);
    __syncthreads();

    if (t < 40) {
        float l = bc3[t];
        for (int c = 0; c < 256; ++c) l = fmaf(sh2[c], Wc3[c * 40 + t], l);
        slog[t] = l;
    }
    float a2 = bd1[t];
    for (int c = 0; c < 256; ++c) a2 = fmaf(sf[c], Wd1[c * 256 + t], a2);
    a2 = fmaxf(a2, 0.f);
    __syncthreads();
    sh[t] = a2;
    __syncthreads();
    if (t < 2) {
        float l = bd2[t];
        for (int c = 0; c < 256; ++c) l = fmaf(sh[c], Wd2[c * 2 + t], l);
        sd[t] = l;
    }
    __syncthreads();

    if (t < 40) {
        float mx = -FLT_MAX;
        for (int j = 0; j < 40; ++j) mx = fmaxf(mx, slog[j]);
        float se = 0.f;
        for (int j = 0; j < 40; ++j) se += expf(slog[j] - mx);
        out[b * 40 + t] = slog[t] - mx - logf(se);
    }
    if (t < 2) {
        float mx = fmaxf(sd[0], sd[1]);
        float se = expf(sd[0] - mx) + expf(sd[1] - mx);
        out[NB * 40 + b * 2 + t] = sd[t] - mx - logf(se);
    }
}

// ---------------- stream/event singletons ----------------
static cudaStream_t g_s2;
static cudaEvent_t g_evA, g_evP2, g_evP3;
static bool g_init = []() {
    cudaStreamCreateWithFlags(&g_s2, cudaStreamNonBlocking);
    cudaEventCreateWithFlags(&g_evA,  cudaEventDisableTiming);
    cudaEventCreateWithFlags(&g_evP2, cudaEventDisableTiming);
    cudaEventCreateWithFlags(&g_evP3, cudaEventDisableTiming);
    return true;
}();

// ---------------- launch ----------------
extern "C" void kernel_launch(void* const* d_in, const int* in_sizes, int n_in,
                              void* d_out, int out_size)
{
    const float* pos = (const float*)d_in[0];
    const float* W1a = (const float*)d_in[1];  const float* b1a = (const float*)d_in[2];
    const float* W1b = (const float*)d_in[3];  const float* b1b = (const float*)d_in[4];
    const float* W2a = (const float*)d_in[5];  const float* b2a = (const float*)d_in[6];
    const float* W2b = (const float*)d_in[7];  const float* b2b = (const float*)d_in[8];
    const float* W3a = (const float*)d_in[9];  const float* b3a = (const float*)d_in[10];
    const float* W3b = (const float*)d_in[11]; const float* b3b = (const float*)d_in[12];
    const float* Wc1 = (const float*)d_in[13]; const float* bc1 = (const float*)d_in[14];
    const float* Wc2 = (const float*)d_in[15]; const float* bc2 = (const float*)d_in[16];
    const float* Wc3 = (const float*)d_in[17]; const float* bc3 = (const float*)d_in[18];
    const float* Wd1 = (const float*)d_in[19]; const float* bd1 = (const float*)d_in[20];
    const float* Wd2 = (const float*)d_in[21]; const float* bd2 = (const float*)d_in[22];
    float* out = (float*)d_out;

    void *p_idx1, *p_cnt1, *p_a1, *p_x1, *p_fi1, *p_pos2, *p_x2g, *p_a2,
         *p_idx2, *p_cnt2, *p_x2, *p_fi2, *p_pos3, *p_x3g, *p_a3,
         *p_idx3, *p_cnt3, *p_x3, *p_pm3, *p_w1, *p_w2, *p_w3,
         *p_ps1, *p_si1, *p_bo1, *p_ps2, *p_si2, *p_bo2;
    cudaGetSymbolAddress(&p_idx1, g_idx1);
    cudaGetSymbolAddress(&p_cnt1, g_cnt1);
    cudaGetSymbolAddress(&p_a1,   g_a1);
    cudaGetSymbolAddress(&p_x1,   g_x1);
    cudaGetSymbolAddress(&p_fi1,  g_fi1);
    cudaGetSymbolAddress(&p_pos2, g_pos2);
    cudaGetSymbolAddress(&p_x2g,  g_x2g);
    cudaGetSymbolAddress(&p_a2,   g_a2);
    cudaGetSymbolAddress(&p_idx2, g_idx2);
    cudaGetSymbolAddress(&p_cnt2, g_cnt2);
    cudaGetSymbolAddress(&p_x2,   g_x2);
    cudaGetSymbolAddress(&p_fi2,  g_fi2);
    cudaGetSymbolAddress(&p_pos3, g_pos3);
    cudaGetSymbolAddress(&p_x3g,  g_x3g);
    cudaGetSymbolAddress(&p_a3,   g_a3);
    cudaGetSymbolAddress(&p_idx3, g_idx3);
    cudaGetSymbolAddress(&p_cnt3, g_cnt3);
    cudaGetSymbolAddress(&p_x3,   g_x3);
    cudaGetSymbolAddress(&p_pm3,  g_perm3);
    cudaGetSymbolAddress(&p_w1,   g_w2t1);
    cudaGetSymbolAddress(&p_w2,   g_w2t2);
    cudaGetSymbolAddress(&p_w3,   g_w2t3);
    cudaGetSymbolAddress(&p_ps1,  g_ps1);
    cudaGetSymbolAddress(&p_si1,  g_si1);
    cudaGetSymbolAddress(&p_bo1,  g_bo1);
    cudaGetSymbolAddress(&p_ps2,  g_ps2);
    cudaGetSymbolAddress(&p_si2,  g_si2);
    cudaGetSymbolAddress(&p_bo2,  g_bo2);

    const int smFps1 = N1 * 12 + 256;
    const int smFps2 = N2 * 12 + 256;
    const int smKnn  = 512 * 16;
    const int shc1 = 4 * (64 * 40 + 64)  * 4;
    const int shc2 = 2 * (128 * 40 + 128) * 4;
    const int shc3 = 1 * (256 * 40 + 256) * 4;
    cudaFuncSetAttribute(fps_kernel<8>,
                         cudaFuncAttributeMaxDynamicSharedMemorySize, 50176);

    const float r1 = 0.2f, r2 = 0.4f, r3 = 1.0f;

    // ======== fork: FPS spine on s2 (needs only pos) ======================
    cudaEventRecord(g_evA, 0);
    cudaStreamWaitEvent(g_s2, g_evA, 0);
    fps_kernel<8><<<NB, 512, smFps1, g_s2>>>(pos, N2, (int*)p_fi1);
    posgather_kernel<<<(NB * N2 * 3 + 255) / 256, 256, 0, g_s2>>>(
        pos, (int*)p_fi1, (float*)p_pos2, N1, N2);
    cudaEventRecord(g_evP2, g_s2);
    fps_kernel<4><<<NB, 512, smFps2, g_s2>>>((float*)p_pos2, N3, (int*)p_fi2);
    posgather_kernel<<<(NB * N3 * 3 + 255) / 256, 256, 0, g_s2>>>(
        (float*)p_pos2, (int*)p_fi2, (float*)p_pos3, N2, N3);
    cudaEventRecord(g_evP3, g_s2);

    // ======== main stream ================================================
    // level 1
    binsort2_kernel<5><<<NB, 256>>>(pos, N1, (float4*)p_ps1, (int*)p_si1,
                                    (int*)p_bo1);
    w2t_pre_kernel<64, 64><<<16, 256>>>(W1b, (u32*)p_w1);
    w2t_pre_kernel<128, 128><<<64, 256>>>(W2b, (u32*)p_w2);
    w2t_pre_kernel<256, 256><<<256, 256>>>(W3b, (u32*)p_w3);
    node_pre_kernel<0, 64><<<(NB * N1 * 64) / 256, 256>>>(
        nullptr, pos, W1a, b1a, (float*)p_a1, NB * N1);
    knnb_kernel<5, 1><<<(N1 / 512) * NB, 512>>>(
        (const float4*)p_ps1, (int*)p_si1, (int*)p_bo1, N1, r1 * r1,
        (int*)p_idx1, (int*)p_cnt1);
    conv_mma_kernel<64, 64><<<dim3(N1 / 4, NB), 256, shc1>>>(
        (float*)p_a1, pos, (int*)p_idx1, (int*)p_cnt1,
        W1a, (u32*)p_w1, b1b, (float*)p_x1, N1);

    // level 2
    cudaStreamWaitEvent(0, g_evP2, 0);
    binsort2_kernel<4><<<NB, 256>>>((float*)p_pos2, N2, (float4*)p_ps2,
                                    (int*)p_si2, (int*)p_bo2);
    knnb_kernel<4, 2><<<(N2 / 512) * NB, 512>>>(
        (const float4*)p_ps2, (int*)p_si2, (int*)p_bo2, N2, r2 * r2,
        (int*)p_idx2, (int*)p_cnt2);
    xgather_kernel<<<512, 256>>>((float*)p_x1, (int*)p_fi1,
                                 (float*)p_x2g, N1, N2, 64);
    node_pre_kernel<64, 128><<<(NB * N2 * 128) / 256, 256>>>(
        (float*)p_x2g, (float*)p_pos2, W2a, b2a, (float*)p_a2, NB * N2);
    conv_mma_kernel<128, 128><<<dim3(N2 / 2, NB), 256, shc2>>>(
        (float*)p_a2, (float*)p_pos2, (int*)p_idx2, (int*)p_cnt2,
        W2a + 64 * 128, (u32*)p_w2, b2b, (float*)p_x2, N2);

    // level 3
    cudaStreamWaitEvent(0, g_evP3, 0);
    binsort_kernel<4><<<NB, 256>>>((float*)p_pos3, N3, (int*)p_pm3);
    knn_kernel<<<(N3 / 512) * NB, 512, smKnn>>>(
        (float*)p_pos3, N3, r3 * r3, (int*)p_idx3, (int*)p_cnt3, (int*)p_pm3);
    xgather_kernel<<<512, 256>>>((float*)p_x2, (int*)p_fi2,
                                 (float*)p_x3g, N2, N3, 128);
    node_pre_kernel<128, 256><<<(NB * N3 * 256) / 256, 256>>>(
        (float*)p_x3g, (float*)p_pos3, W3a, b3a, (float*)p_a3, NB * N3);
    conv_mma_kernel<256, 256><<<dim3(N3, NB), 256, shc3>>>(
        (float*)p_a3, (float*)p_pos3, (int*)p_idx3, (int*)p_cnt3,
        W3a + 128 * 256, (u32*)p_w3, b3b, (float*)p_x3, N3);

    // head
    head_kernel<<<NB, 256>>>((float*)p_x3, Wc1, bc1, Wc2, bc2, Wc3, bc3,
                             Wd1, bd1, Wd2, bd2, out);

    (void)in_sizes; (void)n_in; (void)out_size; (void)g_init;
}

// round 17
// speedup vs baseline: 1.6859x; 1.0773x over previous
#include <cuda_runtime.h>
#include <math.h>
#include <float.h>

typedef unsigned int u32;

static constexpr int NB = 8, N1 = 4096, N2 = 2048, N3 = 512, KNN = 32;

// ---------------- scratch ----------------
__device__ int   g_idx1[NB * N1 * KNN];
__device__ int   g_cnt1[NB * N1];
__device__ float g_a1  [NB * N1 * 64];
__device__ float g_x1  [NB * N1 * 64];
__device__ int   g_fi1 [NB * N2];
__device__ float g_pos2[NB * N2 * 3];
__device__ float g_x2g [NB * N2 * 64];
__device__ float g_a2  [NB * N2 * 128];
__device__ int   g_idx2[NB * N2 * KNN];
__device__ int   g_cnt2[NB * N2];
__device__ float g_x2  [NB * N2 * 128];
__device__ int   g_fi2 [NB * N3];
__device__ float g_pos3[NB * N3 * 3];
__device__ float g_x3g [NB * N3 * 128];
__device__ float g_a3  [NB * N3 * 256];
__device__ int   g_idx3[NB * N3 * KNN];
__device__ int   g_cnt3[NB * N3];
__device__ float g_x3  [NB * N3 * 256];
__device__ int   g_perm3[NB * N3];
__device__ u32   g_w2t1[4096];
__device__ u32   g_w2t2[16384];
__device__ u32   g_w2t3[65536];
// binned-KNN structures (levels 1-2)
__device__ float4 g_ps1[NB * N1];
__device__ int    g_si1[NB * N1];
__device__ int    g_bo1[NB * 126];
__device__ float4 g_ps2[NB * N2];
__device__ int    g_si2[NB * N2];
__device__ int    g_bo2[NB * 65];

// ---------------- tf32 helpers ----------------
__device__ __forceinline__ u32 f2tf32(float f) {
    u32 r; asm("cvt.rna.tf32.f32 %0,%1;" : "=r"(r) : "f"(f)); return r;
}
__device__ __forceinline__ void mma_tf32(float* d, const u32* A, u32 b0, u32 b1) {
    asm("mma.sync.aligned.m16n8k8.row.col.f32.tf32.tf32.f32 "
        "{%0,%1,%2,%3},{%4,%5,%6,%7},{%8,%9},{%0,%1,%2,%3};"
        : "+f"(d[0]), "+f"(d[1]), "+f"(d[2]), "+f"(d[3])
        : "r"(A[0]), "r"(A[1]), "r"(A[2]), "r"(A[3]), "r"(b0), "r"(b1));
}

// ---------------- W2 -> tf32 fragment-major precompute ----------------
template <int CHID, int COUT>
__global__ void __launch_bounds__(256)
w2t_pre_kernel(const float* __restrict__ W2, u32* __restrict__ W2T)
{
    constexpr int NW = COUT / 32;
    int tid = blockIdx.x * 256 + threadIdx.x;
    int lane8 = tid & 255;
    int lane = lane8 >> 3, n = (lane8 & 7) >> 1, r = lane8 & 1;
    int rest = tid >> 8;
    int w = rest % NW, kt = rest / NW;
    int k = kt * 8 + (lane & 3) + r * 4;
    int c = w * 32 + n * 8 + (lane >> 2);
    W2T[tid] = f2tf32(W2[k * COUT + c]);
}

// ---------------- classic binsort (perm only; level 3) ----------------
template <int NBIN>
__global__ void __launch_bounds__(256)
binsort_kernel(const float* __restrict__ pos, int N, int* __restrict__ perm)
{
    constexpr int B3 = NBIN * NBIN * NBIN;
    __shared__ int hist[B3];
    __shared__ int offs[B3];
    const int b = blockIdx.x, t = threadIdx.x;
    const float* pb = pos + (size_t)b * N * 3;

    for (int e = t; e < B3; e += 256) hist[e] = 0;
    __syncthreads();
    for (int i = t; i < N; i += 256) {
        int ix = min(NBIN - 1, max(0, (int)(pb[i * 3 + 0] * NBIN)));
        int iy = min(NBIN - 1, max(0, (int)(pb[i * 3 + 1] * NBIN)));
        int iz = min(NBIN - 1, max(0, (int)(pb[i * 3 + 2] * NBIN)));
        atomicAdd(&hist[(ix * NBIN + iy) * NBIN + iz], 1);
    }
    __syncthreads();
    if (t == 0) {
        int acc = 0;
        for (int k = 0; k < B3; ++k) { offs[k] = acc; acc += hist[k]; }
    }
    __syncthreads();
    for (int e = t; e < B3; e += 256) hist[e] = 0;
    __syncthreads();
    for (int i = t; i < N; i += 256) {
        int ix = min(NBIN - 1, max(0, (int)(pb[i * 3 + 0] * NBIN)));
        int iy = min(NBIN - 1, max(0, (int)(pb[i * 3 + 1] * NBIN)));
        int iz = min(NBIN - 1, max(0, (int)(pb[i * 3 + 2] * NBIN)));
        int key = (ix * NBIN + iy) * NBIN + iz;
        int r = offs[key] + atomicAdd(&hist[key], 1);
        perm[b * N + r] = i;
    }
}

// ---------------- extended binsort: sorted candidates + offsets ----------
template <int NBIN>
__global__ void __launch_bounds__(256)
binsort2_kernel(const float* __restrict__ pos, int N,
                float4* __restrict__ ps, int* __restrict__ sidx,
                int* __restrict__ boff)
{
    constexpr int B3 = NBIN * NBIN * NBIN;
    __shared__ int hist[B3];
    __shared__ int offs[B3];
    const int b = blockIdx.x, t = threadIdx.x;
    const float* pb = pos + (size_t)b * N * 3;

    for (int e = t; e < B3; e += 256) hist[e] = 0;
    __syncthreads();
    for (int i = t; i < N; i += 256) {
        int ix = min(NBIN - 1, max(0, (int)(pb[i * 3 + 0] * NBIN)));
        int iy = min(NBIN - 1, max(0, (int)(pb[i * 3 + 1] * NBIN)));
        int iz = min(NBIN - 1, max(0, (int)(pb[i * 3 + 2] * NBIN)));
        atomicAdd(&hist[(ix * NBIN + iy) * NBIN + iz], 1);
    }
    __syncthreads();
    if (t == 0) {
        int acc = 0;
        for (int k = 0; k < B3; ++k) { offs[k] = acc; acc += hist[k]; }
    }
    __syncthreads();
    for (int e = t; e < B3; e += 256) boff[b * (B3 + 1) + e] = offs[e];
    if (t == 0) boff[b * (B3 + 1) + B3] = N;
    for (int e = t; e < B3; e += 256) hist[e] = 0;
    __syncthreads();
    for (int i = t; i < N; i += 256) {
        float x = pb[i * 3 + 0], y = pb[i * 3 + 1], z = pb[i * 3 + 2];
        int ix = min(NBIN - 1, max(0, (int)(x * NBIN)));
        int iy = min(NBIN - 1, max(0, (int)(y * NBIN)));
        int iz = min(NBIN - 1, max(0, (int)(z * NBIN)));
        int key = (ix * NBIN + iy) * NBIN + iz;
        int r = offs[key] + atomicAdd(&hist[key], 1);
        float sq = __fadd_rn(__fadd_rn(__fmul_rn(x, x), __fmul_rn(y, y)),
                             __fmul_rn(z, z));
        ps[(size_t)b * N + r] = make_float4(x, y, z, sq);
        sidx[b * N + r] = i;
    }
}

// ---------------- per-node a_j = [x_j, pos_j] @ W1 + b1 ----------------
template <int CINX, int CHID>
__global__ void __launch_bounds__(256)
node_pre_kernel(const float* __restrict__ x, const float* __restrict__ pos,
                const float* __restrict__ W1, const float* __restrict__ b1,
                float* __restrict__ a, int nNodes)
{
    int tid = blockIdx.x * 256 + threadIdx.x;
    if (tid >= nNodes * CHID) return;
    int node = tid / CHID, c = tid - node * CHID;
    float acc = b1[c];
    if (CINX > 0) {
        const float* xr = x + (size_t)node * CINX;
#pragma unroll 4
        for (int f = 0; f < CINX; ++f)
            acc = fmaf(xr[f], W1[f * CHID + c], acc);
    }
    const float* pr = pos + (size_t)node * 3;
    acc = fmaf(pr[0], W1[(CINX + 0) * CHID + c], acc);
    acc = fmaf(pr[1], W1[(CINX + 1) * CHID + c], acc);
    acc = fmaf(pr[2], W1[(CINX + 2) * CHID + c], acc);
    a[tid] = acc;
}

// ---------------- binned KNN (levels 1-2) ----------------
template <int NBIN, int S>
__global__ void __launch_bounds__(512, 1)
knnb_kernel(const float4* __restrict__ ps, const int* __restrict__ sidx,
            const int* __restrict__ boff, int N, float r2v,
            int* __restrict__ oidx, int* __restrict__ ocnt)
{
    constexpr int B3 = NBIN * NBIN * NBIN;
    const int b = blockIdx.x % NB, qb = blockIdx.x / NB;
    const float4* P = ps + (size_t)b * N;
    const int* SI = sidx + (size_t)b * N;
    const int* BO = boff + b * (B3 + 1);
    const int rank = qb * 512 + threadIdx.x;

    float4 qv = P[rank];
    const int qi = SI[rank];
    const float xi = qv.x, yi = qv.y, zi = qv.z, sqi = qv.w;
    const float m2x = -2.f * xi, m2y = -2.f * yi, m2z = -2.f * zi;
    const int bx = min(NBIN - 1, max(0, (int)(xi * NBIN)));
    const int by = min(NBIN - 1, max(0, (int)(yi * NBIN)));
    const int bz = min(NBIN - 1, max(0, (int)(zi * NBIN)));

    float bd[KNN];
    int   bi_[KNN];
#pragma unroll
    for (int k = 0; k < KNN; ++k) { bd[k] = FLT_MAX; bi_[k] = 0; }
    float worst = FLT_MAX;

    for (int s = 0; s <= S; ++s) {
        for (int dx = -s; dx <= s; ++dx) {
            int nx = bx + dx;
            if (nx < 0 || nx >= NBIN) continue;
            int adx = dx < 0 ? -dx : dx;
            for (int dy = -s; dy <= s; ++dy) {
                int ny = by + dy;
                if (ny < 0 || ny >= NBIN) continue;
                int ady = dy < 0 ? -dy : dy;
                for (int dz = -s; dz <= s; ++dz) {
                    int nz = bz + dz;
                    if (nz < 0 || nz >= NBIN) continue;
                    int adz = dz < 0 ? -dz : dz;
                    int cheb = max(adx, max(ady, adz));
                    if (cheb != s) continue;
                    int key = (nx * NBIN + ny) * NBIN + nz;
                    int rEnd = BO[key + 1];
                    for (int r = BO[key]; r < rEnd; ++r) {
                        float4 c = P[r];
                        float d2 = sqi + fmaf(m2x, c.x,
                                       fmaf(m2y, c.y, fmaf(m2z, c.z, c.w)));
                        if (d2 <= r2v && d2 < worst) {
                            int j = SI[r];
                            if (j != qi) {
#pragma unroll
                                for (int k = KNN - 1; k > 0; --k) {
                                    if (bd[k - 1] > d2)  { bd[k] = bd[k - 1]; bi_[k] = bi_[k - 1]; }
                                    else if (bd[k] > d2) { bd[k] = d2;        bi_[k] = j; }
                                }
                                if (bd[0] > d2)          { bd[0] = d2;        bi_[0] = j; }
                                worst = bd[KNN - 1];
                            }
                        }
                    }
                }
            }
        }
    }
    int cnt = 0;
#pragma unroll
    for (int k = 0; k < KNN; ++k) cnt += (bd[k] <= r2v) ? 1 : 0;
    ocnt[b * N + qi] = cnt;
    const int base = (b * N + qi) * KNN;
#pragma unroll
    for (int k = 0; k < KNN; ++k) oidx[base + k] = bi_[k];
}

// ---------------- classic tile KNN (level 3) ----------------
__device__ void knn_dev(const float* __restrict__ pb, int N, float r2v,
                        int* __restrict__ oidx, int* __restrict__ ocnt,
                        int qb, const int* __restrict__ perm, float4* sj)
{
    const int t = threadIdx.x;
    const int i = perm[qb * 512 + t];
    const float xi = pb[i * 3 + 0], yi = pb[i * 3 + 1], zi = pb[i * 3 + 2];
    const float sqi = __fadd_rn(__fadd_rn(__fmul_rn(xi, xi), __fmul_rn(yi, yi)),
                                __fmul_rn(zi, zi));
    const float m2x = -2.f * xi, m2y = -2.f * yi, m2z = -2.f * zi;

    float bd[KNN];
    int   bi_[KNN];
#pragma unroll
    for (int k = 0; k < KNN; ++k) { bd[k] = FLT_MAX; bi_[k] = 0; }
    float worst = FLT_MAX;

    for (int t0 = 0; t0 < N; t0 += 512) {
        __syncthreads();
        {
            int j = t0 + t;
            float x = pb[j * 3 + 0], y = pb[j * 3 + 1], z = pb[j * 3 + 2];
            float sq = __fadd_rn(__fadd_rn(__fmul_rn(x, x), __fmul_rn(y, y)),
                                 __fmul_rn(z, z));
            sj[t] = make_float4(x, y, z, sq);
        }
        __syncthreads();
#pragma unroll 2
        for (int jj = 0; jj < 512; ++jj) {
            float4 q = sj[jj];
            float d2 = sqi + fmaf(m2x, q.x, fmaf(m2y, q.y, fmaf(m2z, q.z, q.w)));
            int j = t0 + jj;
            if (d2 <= r2v && d2 < worst && j != i) {
#pragma unroll
                for (int k = KNN - 1; k > 0; --k) {
                    if (bd[k - 1] > d2)  { bd[k] = bd[k - 1]; bi_[k] = bi_[k - 1]; }
                    else if (bd[k] > d2) { bd[k] = d2;        bi_[k] = j; }
                }
                if (bd[0] > d2)          { bd[0] = d2;        bi_[0] = j; }
                worst = bd[KNN - 1];
            }
        }
    }
    int cnt = 0;
#pragma unroll
    for (int k = 0; k < KNN; ++k) cnt += (bd[k] <= r2v) ? 1 : 0;
    ocnt[i] = cnt;
    const int base = i * KNN;
#pragma unroll
    for (int k = 0; k < KNN; ++k) oidx[base + k] = bi_[k];
}

__global__ void __launch_bounds__(512, 1)
knn_kernel(const float* __restrict__ pos, int N, float r2v,
           int* __restrict__ oidx, int* __restrict__ ocnt,
           const int* __restrict__ perm)
{
    extern __shared__ char sm[];
    int b = blockIdx.x % NB, qb = blockIdx.x / NB;
    knn_dev(pos + (size_t)b * N * 3, N, r2v,
            oidx + (size_t)b * N * KNN, ocnt + b * N, qb,
            perm + b * N, (float4*)sm);
}

// ---------------- FPS: 256 threads, P pts/thread, inline pos gather -------
// Fewer warps -> cheaper barrier + leader reduce on the serial chain.
// Selection arithmetic identical to previous rounds (bit-identical output).
template <int P>
__global__ void __launch_bounds__(256, 1)
fps_kernel(const float* __restrict__ pos, int nS, int* __restrict__ fi,
           float* __restrict__ poso)
{
    extern __shared__ char sm[];
    float* smf = (float*)sm;
    const int N = P * 256;
    const float* pb = pos + (size_t)blockIdx.x * N * 3;
    int* out = fi + blockIdx.x * nS;
    float* po = poso + (size_t)blockIdx.x * nS * 3;
    float* spos = smf;
    u32*  svb = (u32*)(smf + N * 3);  // [2][8]
    int*  si  = (int*)(svb + 16);     // [2][8]
    const int t = threadIdx.x, w = t >> 5, l = t & 31;

    for (int e = t; e < N * 3; e += 256) spos[e] = pb[e];
    __syncthreads();

    float px[P], py[P], pz[P], mind[P];
    const float x0 = spos[0], y0 = spos[1], z0 = spos[2];
    float bv = -1.f; int bidx = 0x7fffffff;
#pragma unroll
    for (int p = 0; p < P; ++p) {
        int i = t + p * 256;
        px[p] = spos[i * 3 + 0]; py[p] = spos[i * 3 + 1]; pz[p] = spos[i * 3 + 2];
        float dx = px[p] - x0, dy = py[p] - y0, dz = pz[p] - z0;
        mind[p] = __fadd_rn(__fadd_rn(__fmul_rn(dx, dx), __fmul_rn(dy, dy)),
                            __fmul_rn(dz, dz));
        if (mind[p] > bv) { bv = mind[p]; bidx = i; }
    }
    if (t == 0) {
        out[0] = 0;
        po[0] = x0; po[1] = y0; po[2] = z0;
    }

    int par = 0;
    for (int s = 1; s < nS; ++s) {
        u32 vb = __float_as_uint(bv);                 // mind >= 0 -> monotone
        u32 m  = __reduce_max_sync(0xffffffffu, vb);
        u32 cand = (vb == m) ? (u32)bidx : 0xffffffffu;
        u32 wi = __reduce_min_sync(0xffffffffu, cand);
        if (l == 0) { svb[par * 8 + w] = m; si[par * 8 + w] = (int)wi; }
        __syncthreads();
        u32 v2 = (l < 8) ? svb[par * 8 + l] : 0u;
        u32 i2 = (l < 8) ? (u32)si[par * 8 + l] : 0xffffffffu;
        u32 m2 = __reduce_max_sync(0xffffffffu, v2);
        u32 c2 = (v2 == m2 && l < 8) ? i2 : 0xffffffffu;
        u32 gi = __reduce_min_sync(0xffffffffu, c2);
        const float cx = spos[gi * 3 + 0];
        const float cy = spos[gi * 3 + 1];
        const float cz = spos[gi * 3 + 2];
        if (t == 0) {
            out[s] = (int)gi;
            po[s * 3 + 0] = cx; po[s * 3 + 1] = cy; po[s * 3 + 2] = cz;
        }
        par ^= 1;
        bv = -1.f; bidx = 0x7fffffff;
#pragma unroll
        for (int p = 0; p < P; ++p) {
            float dx = px[p] - cx, dy = py[p] - cy, dz = pz[p] - cz;
            float d = __fadd_rn(__fadd_rn(__fmul_rn(dx, dx), __fmul_rn(dy, dy)),
                                __fmul_rn(dz, dz));
            mind[p] = fminf(mind[p], d);
            if (mind[p] > bv) { bv = mind[p]; bidx = t + p * 256; }
        }
    }
}

// ---------------- feature gather ----------------
__global__ void xgather_kernel(const float* __restrict__ xin,
                               const int* __restrict__ fi,
                               float* __restrict__ xo, int Nin, int Nout, int C)
{
    const int tid = blockIdx.x * blockDim.x + threadIdx.x;
    const int stride = gridDim.x * blockDim.x;
    const int tot = NB * Nout * C;
    for (int e = tid; e < tot; e += stride) {
        int c = e % C, m = (e / C) % Nout, b = e / (C * Nout);
        int j = fi[b * Nout + m];
        xo[e] = xin[((size_t)b * Nin + j) * C + c];
    }
}

// ---------------- PointNetConv on tensor cores ----------------
template <int CHID, int COUT>
__global__ void __launch_bounds__(256)
conv_mma_kernel(const float* __restrict__ a, const float* __restrict__ pos,
                const int* __restrict__ kidx, const int* __restrict__ kcnt,
                const float* __restrict__ W1p, const u32* __restrict__ W2T,
                const float* __restrict__ b2, float* __restrict__ xout, int N)
{
    constexpr int NW  = COUT / 32;
    constexpr int TPG = COUT;
    constexpr int PPB = 256 / TPG;
    constexpr int KT  = CHID / 8;
    constexpr int HS  = 40;
    constexpr int GSZ = CHID * HS + CHID;
    extern __shared__ char sm[];
    float* smem = (float*)sm;
    const int tg = threadIdx.x / TPG;
    const int tp = threadIdx.x % TPG;
    u32*   hTu = (u32*)(smem + tg * GSZ);
    float* scv = smem + tg * GSZ + CHID * HS;
    __shared__ int   sidx[PPB][KNN];
    __shared__ float spi[PPB][3];
    __shared__ int   scnt[PPB];

    const int b = blockIdx.y;
    const int i = blockIdx.x * PPB + tg;

    if (tp < KNN) sidx[tg][tp] = kidx[((size_t)b * N + i) * KNN + tp];
    if (tp == 0)  scnt[tg] = kcnt[b * N + i];
    if (tp < 3)   spi[tg][tp] = pos[((size_t)b * N + i) * 3 + tp];
    __syncthreads();
    const int cnt = scnt[tg];
    const float p0 = spi[tg][0], p1 = spi[tg][1], p2 = spi[tg][2];
    scv[tp] = fmaf(p2, W1p[2 * CHID + tp],
                   fmaf(p1, W1p[CHID + tp], p0 * W1p[tp]));
    __syncthreads();

    const float* ab = a + (size_t)b * N * CHID;
    const float cv = scv[tp];
#pragma unroll
    for (int kq = 0; kq < 8; ++kq) {
        int j0 = sidx[tg][kq * 4 + 0], j1 = sidx[tg][kq * 4 + 1];
        int j2 = sidx[tg][kq * 4 + 2], j3 = sidx[tg][kq * 4 + 3];
        uint4 h;
        h.x = f2tf32(fmaxf(ab[(size_t)j0 * CHID + tp] - cv, 0.f));
        h.y = f2tf32(fmaxf(ab[(size_t)j1 * CHID + tp] - cv, 0.f));
        h.z = f2tf32(fmaxf(ab[(size_t)j2 * CHID + tp] - cv, 0.f));
        h.w = f2tf32(fmaxf(ab[(size_t)j3 * CHID + tp] - cv, 0.f));
        *(uint4*)&hTu[tp * HS + kq * 4] = h;
    }
    __syncthreads();

    const int lane = tp & 31;
    const int w = tp >> 5;
    const int q = lane >> 2, kk = lane & 3;
    const uint4* Wt = (const uint4*)W2T;

    float d[2][4][4];
#pragma unroll
    for (int m = 0; m < 2; ++m)
#pragma unroll
        for (int n = 0; n < 4; ++n)
#pragma unroll
            for (int r = 0; r < 4; ++r) d[m][n][r] = 0.f;

    for (int kt = 0; kt < KT; ++kt) {
        const u32* col0 = hTu + (kt * 8 + kk) * HS;
        const u32* col4 = col0 + 4 * HS;
        u32 A0[4], A1[4];
        A0[0] = col0[q];       A0[1] = col0[q + 8];
        A0[2] = col4[q];       A0[3] = col4[q + 8];
        A1[0] = col0[16 + q];  A1[1] = col0[16 + q + 8];
        A1[2] = col4[16 + q];  A1[3] = col4[16 + q + 8];
        uint4 B0 = Wt[((kt * NW + w) * 32 + lane) * 2 + 0];
        uint4 B1 = Wt[((kt * NW + w) * 32 + lane) * 2 + 1];
        mma_tf32(d[0][0], A0, B0.x, B0.y);
        mma_tf32(d[0][1], A0, B0.z, B0.w);
        mma_tf32(d[0][2], A0, B1.x, B1.y);
        mma_tf32(d[0][3], A0, B1.z, B1.w);
        mma_tf32(d[1][0], A1, B0.x, B0.y);
        mma_tf32(d[1][1], A1, B0.z, B0.w);
        mma_tf32(d[1][2], A1, B1.x, B1.y);
        mma_tf32(d[1][3], A1, B1.z, B1.w);
    }

#pragma unroll
    for (int n = 0; n < 4; ++n) {
        float v0 = -FLT_MAX, v1 = -FLT_MAX;
#pragma unroll
        for (int m = 0; m < 2; ++m) {
            int r0 = m * 16 + q, r1 = r0 + 8;
            if (r0 < cnt) { v0 = fmaxf(v0, d[m][n][0]); v1 = fmaxf(v1, d[m][n][1]); }
            if (r1 < cnt) { v0 = fmaxf(v0, d[m][n][2]); v1 = fmaxf(v1, d[m][n][3]); }
        }
        v0 = fmaxf(v0, __shfl_xor_sync(0xffffffffu, v0, 4));
        v1 = fmaxf(v1, __shfl_xor_sync(0xffffffffu, v1, 4));
        v0 = fmaxf(v0, __shfl_xor_sync(0xffffffffu, v0, 8));
        v1 = fmaxf(v1, __shfl_xor_sync(0xffffffffu, v1, 8));
        v0 = fmaxf(v0, __shfl_xor_sync(0xffffffffu, v0, 16));
        v1 = fmaxf(v1, __shfl_xor_sync(0xffffffffu, v1, 16));
        if (lane < 4) {
            int c = w * 32 + n * 8 + lane * 2;
            float o0 = (cnt > 0) ? fmaxf(v0 + b2[c], 0.f) : 0.f;
            float o1 = (cnt > 0) ? fmaxf(v1 + b2[c + 1], 0.f) : 0.f;
            xout[((size_t)b * N + i) * COUT + c]     = o0;
            xout[((size_t)b * N + i) * COUT + c + 1] = o1;
        }
    }
}

// ---------------- head ----------------
__global__ void head_kernel(const float* __restrict__ x3,
                            const float* __restrict__ Wc1, const float* __restrict__ bc1,
                            const float* __restrict__ Wc2, const float* __restrict__ bc2,
                            const float* __restrict__ Wc3, const float* __restrict__ bc3,
                            const float* __restrict__ Wd1, const float* __restrict__ bd1,
                            const float* __restrict__ Wd2, const float* __restrict__ bd2,
                            float* __restrict__ out)
{
    __shared__ float sf[256], sh[256], sh2[256], slog[40], sd[2];
    const int b = blockIdx.x, t = threadIdx.x;

    float m = -FLT_MAX;
    for (int n = 0; n < N3; ++n)
        m = fmaxf(m, x3[((size_t)b * N3 + n) * 256 + t]);
    sf[t] = m;
    __syncthreads();

    float a = bc1[t];
    for (int c = 0; c < 256; ++c) a = fmaf(sf[c], Wc1[c * 256 + t], a);
    sh[t] = fmaxf(a, 0.f);
    __syncthreads();

    a = bc2[t];
    for (int c = 0; c < 256; ++c) a = fmaf(sh[c], Wc2[c * 256 + t], a);
    sh2[t] = fmaxf(a, 0.f);
    __syncthreads();

    if (t < 40) {
        float l = bc3[t];
        for (int c = 0; c < 256; ++c) l = fmaf(sh2[c], Wc3[c * 40 + t], l);
        slog[t] = l;
    }
    float a2 = bd1[t];
    for (int c = 0; c < 256; ++c) a2 = fmaf(sf[c], Wd1[c * 256 + t], a2);
    a2 = fmaxf(a2, 0.f);
    __syncthreads();
    sh[t] = a2;
    __syncthreads();
    if (t < 2) {
        float l = bd2[t];
        for (int c = 0; c < 256; ++c) l = fmaf(sh[c], Wd2[c * 2 + t], l);
        sd[t] = l;
    }
    __syncthreads();

    if (t < 40) {
        float mx = -FLT_MAX;
        for (int j = 0; j < 40; ++j) mx = fmaxf(mx, slog[j]);
        float se = 0.f;
        for (int j = 0; j < 40; ++j) se += expf(slog[j] - mx);
        out[b * 40 + t] = slog[t] - mx - logf(se);
    }
    if (t < 2) {
        float mx = fmaxf(sd[0], sd[1]);
        float se = expf(sd[0] - mx) + expf(sd[1] - mx);
        out[NB * 40 + b * 2 + t] = sd[t] - mx - logf(se);
    }
}

// ---------------- stream/event singletons ----------------
static cudaStream_t g_s2;
static cudaEvent_t g_evA, g_evP2, g_evP3;
static bool g_init = []() {
    cudaStreamCreateWithFlags(&g_s2, cudaStreamNonBlocking);
    cudaEventCreateWithFlags(&g_evA,  cudaEventDisableTiming);
    cudaEventCreateWithFlags(&g_evP2, cudaEventDisableTiming);
    cudaEventCreateWithFlags(&g_evP3, cudaEventDisableTiming);
    return true;
}();

// ---------------- launch ----------------
extern "C" void kernel_launch(void* const* d_in, const int* in_sizes, int n_in,
                              void* d_out, int out_size)
{
    const float* pos = (const float*)d_in[0];
    const float* W1a = (const float*)d_in[1];  const float* b1a = (const float*)d_in[2];
    const float* W1b = (const float*)d_in[3];  const float* b1b = (const float*)d_in[4];
    const float* W2a = (const float*)d_in[5];  const float* b2a = (const float*)d_in[6];
    const float* W2b = (const float*)d_in[7];  const float* b2b = (const float*)d_in[8];
    const float* W3a = (const float*)d_in[9];  const float* b3a = (const float*)d_in[10];
    const float* W3b = (const float*)d_in[11]; const float* b3b = (const float*)d_in[12];
    const float* Wc1 = (const float*)d_in[13]; const float* bc1 = (const float*)d_in[14];
    const float* Wc2 = (const float*)d_in[15]; const float* bc2 = (const float*)d_in[16];
    const float* Wc3 = (const float*)d_in[17]; const float* bc3 = (const float*)d_in[18];
    const float* Wd1 = (const float*)d_in[19]; const float* bd1 = (const float*)d_in[20];
    const float* Wd2 = (const float*)d_in[21]; const float* bd2 = (const float*)d_in[22];
    float* out = (float*)d_out;

    void *p_idx1, *p_cnt1, *p_a1, *p_x1, *p_fi1, *p_pos2, *p_x2g, *p_a2,
         *p_idx2, *p_cnt2, *p_x2, *p_fi2, *p_pos3, *p_x3g, *p_a3,
         *p_idx3, *p_cnt3, *p_x3, *p_pm3, *p_w1, *p_w2, *p_w3,
         *p_ps1, *p_si1, *p_bo1, *p_ps2, *p_si2, *p_bo2;
    cudaGetSymbolAddress(&p_idx1, g_idx1);
    cudaGetSymbolAddress(&p_cnt1, g_cnt1);
    cudaGetSymbolAddress(&p_a1,   g_a1);
    cudaGetSymbolAddress(&p_x1,   g_x1);
    cudaGetSymbolAddress(&p_fi1,  g_fi1);
    cudaGetSymbolAddress(&p_pos2, g_pos2);
    cudaGetSymbolAddress(&p_x2g,  g_x2g);
    cudaGetSymbolAddress(&p_a2,   g_a2);
    cudaGetSymbolAddress(&p_idx2, g_idx2);
    cudaGetSymbolAddress(&p_cnt2, g_cnt2);
    cudaGetSymbolAddress(&p_x2,   g_x2);
    cudaGetSymbolAddress(&p_fi2,  g_fi2);
    cudaGetSymbolAddress(&p_pos3, g_pos3);
    cudaGetSymbolAddress(&p_x3g,  g_x3g);
    cudaGetSymbolAddress(&p_a3,   g_a3);
    cudaGetSymbolAddress(&p_idx3, g_idx3);
    cudaGetSymbolAddress(&p_cnt3, g_cnt3);
    cudaGetSymbolAddress(&p_x3,   g_x3);
    cudaGetSymbolAddress(&p_pm3,  g_perm3);
    cudaGetSymbolAddress(&p_w1,   g_w2t1);
    cudaGetSymbolAddress(&p_w2,   g_w2t2);
    cudaGetSymbolAddress(&p_w3,   g_w2t3);
    cudaGetSymbolAddress(&p_ps1,  g_ps1);
    cudaGetSymbolAddress(&p_si1,  g_si1);
    cudaGetSymbolAddress(&p_bo1,  g_bo1);
    cudaGetSymbolAddress(&p_ps2,  g_ps2);
    cudaGetSymbolAddress(&p_si2,  g_si2);
    cudaGetSymbolAddress(&p_bo2,  g_bo2);

    const int smFps1 = N1 * 12 + 256;
    const int smFps2 = N2 * 12 + 256;
    const int smKnn  = 512 * 16;
    const int shc1 = 4 * (64 * 40 + 64)  * 4;
    const int shc2 = 2 * (128 * 40 + 128) * 4;
    const int shc3 = 1 * (256 * 40 + 256) * 4;
    cudaFuncSetAttribute(fps_kernel<16>,
                         cudaFuncAttributeMaxDynamicSharedMemorySize, 50176);

    const float r1 = 0.2f, r2 = 0.4f, r3 = 1.0f;

    // ======== fork: FPS spine on s2 (needs only pos; writes pos inline) ===
    cudaEventRecord(g_evA, 0);
    cudaStreamWaitEvent(g_s2, g_evA, 0);
    fps_kernel<16><<<NB, 256, smFps1, g_s2>>>(pos, N2, (int*)p_fi1,
                                              (float*)p_pos2);
    cudaEventRecord(g_evP2, g_s2);
    fps_kernel<8><<<NB, 256, smFps2, g_s2>>>((float*)p_pos2, N3, (int*)p_fi2,
                                             (float*)p_pos3);
    cudaEventRecord(g_evP3, g_s2);

    // ======== main stream ================================================
    // level 1
    binsort2_kernel<5><<<NB, 256>>>(pos, N1, (float4*)p_ps1, (int*)p_si1,
                                    (int*)p_bo1);
    w2t_pre_kernel<64, 64><<<16, 256>>>(W1b, (u32*)p_w1);
    w2t_pre_kernel<128, 128><<<64, 256>>>(W2b, (u32*)p_w2);
    w2t_pre_kernel<256, 256><<<256, 256>>>(W3b, (u32*)p_w3);
    node_pre_kernel<0, 64><<<(NB * N1 * 64) / 256, 256>>>(
        nullptr, pos, W1a, b1a, (float*)p_a1, NB * N1);
    knnb_kernel<5, 1><<<(N1 / 512) * NB, 512>>>(
        (const float4*)p_ps1, (int*)p_si1, (int*)p_bo1, N1, r1 * r1,
        (int*)p_idx1, (int*)p_cnt1);
    conv_mma_kernel<64, 64><<<dim3(N1 / 4, NB), 256, shc1>>>(
        (float*)p_a1, pos, (int*)p_idx1, (int*)p_cnt1,
        W1a, (u32*)p_w1, b1b, (float*)p_x1, N1);

    // level 2
    cudaStreamWaitEvent(0, g_evP2, 0);
    binsort2_kernel<4><<<NB, 256>>>((float*)p_pos2, N2, (float4*)p_ps2,
                                    (int*)p_si2, (int*)p_bo2);
    knnb_kernel<4, 2><<<(N2 / 512) * NB, 512>>>(
        (const float4*)p_ps2, (int*)p_si2, (int*)p_bo2, N2, r2 * r2,
        (int*)p_idx2, (int*)p_cnt2);
    xgather_kernel<<<512, 256>>>((float*)p_x1, (int*)p_fi1,
                                 (float*)p_x2g, N1, N2, 64);
    node_pre_kernel<64, 128><<<(NB * N2 * 128) / 256, 256>>>(
        (float*)p_x2g, (float*)p_pos2, W2a, b2a, (float*)p_a2, NB * N2);
    conv_mma_kernel<128, 128><<<dim3(N2 / 2, NB), 256, shc2>>>(
        (float*)p_a2, (float*)p_pos2, (int*)p_idx2, (int*)p_cnt2,
        W2a + 64 * 128, (u32*)p_w2, b2b, (float*)p_x2, N2);

    // level 3
    cudaStreamWaitEvent(0, g_evP3, 0);
    binsort_kernel<4><<<NB, 256>>>((float*)p_pos3, N3, (int*)p_pm3);
    knn_kernel<<<(N3 / 512) * NB, 512, smKnn>>>(
        (float*)p_pos3, N3, r3 * r3, (int*)p_idx3, (int*)p_cnt3, (int*)p_pm3);
    xgather_kernel<<<512, 256>>>((float*)p_x2, (int*)p_fi2,
                                 (float*)p_x3g, N2, N3, 128);
    node_pre_kernel<128, 256><<<(NB * N3 * 256) / 256, 256>>>(
        (float*)p_x3g, (float*)p_pos3, W3a, b3a, (float*)p_a3, NB * N3);
    conv_mma_kernel<256, 256><<<dim3(N3, NB), 256, shc3>>>(
        (float*)p_a3, (float*)p_pos3, (int*)p_idx3, (int*)p_cnt3,
        W3a + 128 * 256, (u32*)p_w3, b3b, (float*)p_x3, N3);

    // head
    head_kernel<<<NB, 256>>>((float*)p_x3, Wc1, bc1, Wc2, bc2, Wc3, bc3,
                             Wd1, bd1, Wd2, bd2, out);

    (void)in_sizes; (void)n_in; (void)out_size; (void)g_init;
}